// round 4
// baseline (speedup 1.0000x reference)
#include <cuda_runtime.h>
#include <cuda_bf16.h>
#include <cstdint>

// ----------------------------------------------------------------------------
// GCN: L1out = relu(Ahat (x@W1) + b1);  h2 = L1out @ W2;
//      agg2 = relu(Ahat h2 + b2);  out = segment_max(agg2, batch) @ Wfc + bfc
// CSR build overlapped with GEMM1. GEMM1: tf32 mma + cp.async double buffer.
// gather1+GEMM2 fused in one kernel (gather into smem, single-shot K=128 MMA).
// gather2 fused with max-pool (atomicMax epilogue).
// ----------------------------------------------------------------------------

#define N_NODES 50000
#define N_EDGES 800000
#define N_GRAPHS 128
#define IN_DIM 256
#define H1 128
#define H2 64
#define OUT_DIM 10

__device__ int   g_deg[N_NODES];
__device__ int   g_off[N_NODES + 1];
__device__ int   g_cursor[N_NODES];
__device__ float g_dis[N_NODES];
__device__ int2  g_cedge[N_EDGES];          // (row, norm-bits)
__device__ float g_h1[(size_t)N_NODES * H1];
__device__ float g_h2[(size_t)N_NODES * H2];
__device__ float g_pool[N_GRAPHS * H2];

// ---------------------------------------------------------------- utils
__device__ __forceinline__ uint32_t f2tf(float x) {
    uint32_t u;
    asm("cvt.rna.tf32.f32 %0, %1;" : "=r"(u) : "f"(x));
    return u;
}

#define MMA_TF32(d, a, b)                                                     \
    asm volatile(                                                             \
        "mma.sync.aligned.m16n8k8.row.col.f32.tf32.tf32.f32 "                 \
        "{%0,%1,%2,%3},{%4,%5,%6,%7},{%8,%9},{%0,%1,%2,%3};"                  \
        : "+f"((d)[0]), "+f"((d)[1]), "+f"((d)[2]), "+f"((d)[3])              \
        : "r"((a)[0]), "r"((a)[1]), "r"((a)[2]), "r"((a)[3]),                 \
          "r"((b)[0]), "r"((b)[1]))

__device__ __forceinline__ void cp16(uint32_t saddr, const void* gaddr, int sz) {
    asm volatile("cp.async.cg.shared.global [%0], [%1], 16, %2;"
                 :: "r"(saddr), "l"(gaddr), "r"(sz));
}

// ---------------------------------------------------------------- CSR build
__global__ void k_count(const int* __restrict__ col, int* deg) {
    int e = blockIdx.x * blockDim.x + threadIdx.x;
    if (e < N_EDGES) atomicAdd(&deg[col[e]], 1);
}

__global__ void __launch_bounds__(1024)
k_scan(const int* __restrict__ deg, int* __restrict__ off,
       int* __restrict__ cursor, float* __restrict__ dis)
{
    __shared__ int sums[1024];
    const int t = threadIdx.x;
    const int CHUNK = (N_NODES + 1023) / 1024;
    int lo = t * CHUNK; if (lo > N_NODES) lo = N_NODES;
    int hi = lo + CHUNK; if (hi > N_NODES) hi = N_NODES;

    int s = 0;
    for (int i = lo; i < hi; i++) s += deg[i];
    sums[t] = s;
    __syncthreads();
    for (int d = 1; d < 1024; d <<= 1) {
        int v = (t >= d) ? sums[t - d] : 0;
        __syncthreads();
        sums[t] += v;
        __syncthreads();
    }
    int run = (t == 0) ? 0 : sums[t - 1];
    for (int i = lo; i < hi; i++) {
        off[i] = run;
        cursor[i] = run;
        int dg = deg[i];
        dis[i] = rsqrtf((float)(dg + 1));
        run += dg;
    }
    if (t == 1023) off[N_NODES] = run;
}

__global__ void k_fill(const int* __restrict__ row, const int* __restrict__ col,
                       const float* __restrict__ dis, int* cursor,
                       int2* __restrict__ cedge)
{
    int e = blockIdx.x * blockDim.x + threadIdx.x;
    if (e >= N_EDGES) return;
    int r = row[e], c = col[e];
    int p = atomicAdd(&cursor[c], 1);
    cedge[p] = make_int2(r, __float_as_int(dis[r] * dis[c]));
}

// ---------------------------------------------------------------- GEMM1 (tf32, cp.async dbuf)
template<int BM, int BN, int BK, int WARPS, int WARPS_M, int WM, int WN>
__global__ void __launch_bounds__(WARPS * 32)
k_gemm_ca(const float* __restrict__ A, const float* __restrict__ B,
          float* __restrict__ C, int M, int K)
{
    constexpr int MT = WM / 16, NT = WN / 8;
    constexpr int SA = BK + 4;
    constexpr int SB = BN + 8;
    __shared__ float As[2][BM * SA];
    __shared__ float Bs[2][BK * SB];

    const int tid = threadIdx.x, wid = tid >> 5, lane = tid & 31;
    const int wm = wid % WARPS_M, wn = wid / WARPS_M;
    const int g = lane >> 2, tig = lane & 3;
    const int m0 = blockIdx.x * BM;

    float acc[MT][NT][4];
#pragma unroll
    for (int i = 0; i < MT; i++)
#pragma unroll
        for (int j = 0; j < NT; j++)
#pragma unroll
            for (int q = 0; q < 4; q++) acc[i][j][q] = 0.f;

    auto loadTiles = [&](int buf, int k0) {
#pragma unroll
        for (int i = tid; i < BM * BK / 4; i += WARPS * 32) {
            int r = i / (BK / 4), c4 = i % (BK / 4);
            cp16((uint32_t)__cvta_generic_to_shared(&As[buf][r * SA + c4 * 4]),
                 A + (size_t)(m0 + r) * K + k0 + c4 * 4,
                 (m0 + r < M) ? 16 : 0);
        }
#pragma unroll
        for (int i = tid; i < BK * BN / 4; i += WARPS * 32) {
            int kk = i / (BN / 4), c4 = i % (BN / 4);
            cp16((uint32_t)__cvta_generic_to_shared(&Bs[buf][kk * SB + c4 * 4]),
                 B + (size_t)(k0 + kk) * BN + c4 * 4, 16);
        }
        asm volatile("cp.async.commit_group;");
    };

    const int nk = K / BK;
    loadTiles(0, 0);
    for (int t = 0; t < nk; t++) {
        if (t + 1 < nk) {
            loadTiles((t + 1) & 1, (t + 1) * BK);
            asm volatile("cp.async.wait_group 1;");
        } else {
            asm volatile("cp.async.wait_group 0;");
        }
        __syncthreads();
        const int buf = t & 1;

#pragma unroll
        for (int kk = 0; kk < BK / 8; kk++) {
            uint32_t af[MT][4], bf[NT][2];
#pragma unroll
            for (int mt = 0; mt < MT; mt++) {
                int r = wm * WM + mt * 16;
                af[mt][0] = f2tf(As[buf][(r + g)     * SA + kk * 8 + tig]);
                af[mt][1] = f2tf(As[buf][(r + g + 8) * SA + kk * 8 + tig]);
                af[mt][2] = f2tf(As[buf][(r + g)     * SA + kk * 8 + tig + 4]);
                af[mt][3] = f2tf(As[buf][(r + g + 8) * SA + kk * 8 + tig + 4]);
            }
#pragma unroll
            for (int nt = 0; nt < NT; nt++) {
                int c = wn * WN + nt * 8;
                bf[nt][0] = f2tf(Bs[buf][(kk * 8 + tig)     * SB + c + g]);
                bf[nt][1] = f2tf(Bs[buf][(kk * 8 + tig + 4) * SB + c + g]);
            }
#pragma unroll
            for (int mt = 0; mt < MT; mt++)
#pragma unroll
                for (int nt = 0; nt < NT; nt++)
                    MMA_TF32(acc[mt][nt], af[mt], bf[nt]);
        }
        __syncthreads();
    }

#pragma unroll
    for (int mt = 0; mt < MT; mt++) {
        int r0 = m0 + wm * WM + mt * 16 + g;
#pragma unroll
        for (int nt = 0; nt < NT; nt++) {
            int c = wn * WN + nt * 8 + 2 * tig;
            if (r0 < M)
                *(float2*)(C + (size_t)r0 * BN + c) =
                    make_float2(acc[mt][nt][0], acc[mt][nt][1]);
            if (r0 + 8 < M)
                *(float2*)(C + (size_t)(r0 + 8) * BN + c) =
                    make_float2(acc[mt][nt][2], acc[mt][nt][3]);
        }
    }
}

// ---------------------------------------------------------------- fused gather1 + GEMM2
// Per block: gather 128 rows of relu(Ahat h1 + b1) into smem (tf32), then one
// K=128 MMA pass against W2 (preloaded via cp.async during the gather).
__global__ void __launch_bounds__(256)
k_gather_gemm2(const float* __restrict__ h1, const float* __restrict__ W2,
               float* __restrict__ h2, const int* __restrict__ off,
               const int2* __restrict__ ce, const float* __restrict__ dis,
               const float* __restrict__ b1)
{
    constexpr int SA = 132;   // 128 + 4
    constexpr int SB = 72;    // 64 + 8
    extern __shared__ float smem[];
    uint32_t* As = (uint32_t*)smem;            // 128 * SA
    float*    Bs = smem + 128 * SA;            // 128 * SB

    const int tid = threadIdx.x, wid = tid >> 5, lane = tid & 31;
    const int m0 = blockIdx.x * 128;

    // preload W2 [128,64] (overlaps with gather)
#pragma unroll
    for (int i = tid; i < 128 * 64 / 4; i += 256) {
        int kk = i / 16, c4 = i % 16;
        cp16((uint32_t)__cvta_generic_to_shared(&Bs[kk * SB + c4 * 4]),
             W2 + kk * 64 + c4 * 4, 16);
    }
    asm volatile("cp.async.commit_group;");

    // gather phase: warp w handles local rows w*16 .. w*16+15
    float4 bb = *(const float4*)(b1 + lane * 4);
    for (int t = 0; t < 16; t++) {
        int lr = wid * 16 + t;
        int node = m0 + lr;
        float4 acc = make_float4(0.f, 0.f, 0.f, 0.f);
        if (node < N_NODES) {
            float d = dis[node];
            float dd = d * d;
            acc = *(const float4*)(h1 + (size_t)node * 128 + lane * 4);
            acc.x *= dd; acc.y *= dd; acc.z *= dd; acc.w *= dd;
            int s = off[node], e = off[node + 1];
            int j = s;
            for (; j + 1 < e; j += 2) {
                int2 p0 = __ldg(&ce[j]);
                int2 p1 = __ldg(&ce[j + 1]);
                float n0 = __int_as_float(p0.y), n1 = __int_as_float(p1.y);
                float4 v0 = *(const float4*)(h1 + (size_t)p0.x * 128 + lane * 4);
                float4 v1 = *(const float4*)(h1 + (size_t)p1.x * 128 + lane * 4);
                acc.x = fmaf(v0.x, n0, acc.x); acc.y = fmaf(v0.y, n0, acc.y);
                acc.z = fmaf(v0.z, n0, acc.z); acc.w = fmaf(v0.w, n0, acc.w);
                acc.x = fmaf(v1.x, n1, acc.x); acc.y = fmaf(v1.y, n1, acc.y);
                acc.z = fmaf(v1.z, n1, acc.z); acc.w = fmaf(v1.w, n1, acc.w);
            }
            if (j < e) {
                int2 p = __ldg(&ce[j]);
                float n = __int_as_float(p.y);
                float4 v = *(const float4*)(h1 + (size_t)p.x * 128 + lane * 4);
                acc.x = fmaf(v.x, n, acc.x); acc.y = fmaf(v.y, n, acc.y);
                acc.z = fmaf(v.z, n, acc.z); acc.w = fmaf(v.w, n, acc.w);
            }
            acc.x = fmaxf(acc.x + bb.x, 0.f); acc.y = fmaxf(acc.y + bb.y, 0.f);
            acc.z = fmaxf(acc.z + bb.z, 0.f); acc.w = fmaxf(acc.w + bb.w, 0.f);
        }
        uint32_t* p = &As[lr * SA + lane * 4];
        p[0] = f2tf(acc.x); p[1] = f2tf(acc.y); p[2] = f2tf(acc.z); p[3] = f2tf(acc.w);
    }
    asm volatile("cp.async.wait_group 0;");
    __syncthreads();

    // MMA phase: 8 warps, warp tile 32x32 (wm 0..3, wn 0..1)
    const int wm = wid % 4, wn = wid / 4;
    const int g = lane >> 2, tig = lane & 3;
    float acc[2][4][4];
#pragma unroll
    for (int i = 0; i < 2; i++)
#pragma unroll
        for (int j = 0; j < 4; j++)
#pragma unroll
            for (int q = 0; q < 4; q++) acc[i][j][q] = 0.f;

#pragma unroll
    for (int kk = 0; kk < 16; kk++) {
        uint32_t af[2][4], bf[4][2];
#pragma unroll
        for (int mt = 0; mt < 2; mt++) {
            int r = wm * 32 + mt * 16;
            af[mt][0] = As[(r + g)     * SA + kk * 8 + tig];
            af[mt][1] = As[(r + g + 8) * SA + kk * 8 + tig];
            af[mt][2] = As[(r + g)     * SA + kk * 8 + tig + 4];
            af[mt][3] = As[(r + g + 8) * SA + kk * 8 + tig + 4];
        }
#pragma unroll
        for (int nt = 0; nt < 4; nt++) {
            int c = wn * 32 + nt * 8;
            bf[nt][0] = f2tf(Bs[(kk * 8 + tig)     * SB + c + g]);
            bf[nt][1] = f2tf(Bs[(kk * 8 + tig + 4) * SB + c + g]);
        }
#pragma unroll
        for (int mt = 0; mt < 2; mt++)
#pragma unroll
            for (int nt = 0; nt < 4; nt++)
                MMA_TF32(acc[mt][nt], af[mt], bf[nt]);
    }

#pragma unroll
    for (int mt = 0; mt < 2; mt++) {
        int r0 = m0 + wm * 32 + mt * 16 + g;
#pragma unroll
        for (int nt = 0; nt < 4; nt++) {
            int c = wn * 32 + nt * 8 + 2 * tig;
            if (r0 < N_NODES)
                *(float2*)(h2 + (size_t)r0 * 64 + c) =
                    make_float2(acc[mt][nt][0], acc[mt][nt][1]);
            if (r0 + 8 < N_NODES)
                *(float2*)(h2 + (size_t)(r0 + 8) * 64 + c) =
                    make_float2(acc[mt][nt][2], acc[mt][nt][3]);
        }
    }
}

// ---------------------------------------------------------------- gather2 + max-pool
__global__ void k_gather64pool(const float* __restrict__ h2,
                               const int* __restrict__ off, const int2* __restrict__ ce,
                               const float* __restrict__ dis, const float* __restrict__ b2,
                               const int* __restrict__ batch, float* __restrict__ pool)
{
    int node = (blockIdx.x * blockDim.x + threadIdx.x) >> 5;
    int lane = threadIdx.x & 31;
    if (node >= N_NODES) return;

    float d = dis[node];
    float dd = d * d;
    float2 acc = *(const float2*)(h2 + (size_t)node * 64 + lane * 2);
    acc.x *= dd; acc.y *= dd;

    int s = off[node], e = off[node + 1];
    int j = s;
    for (; j + 1 < e; j += 2) {
        int2 p0 = __ldg(&ce[j]);
        int2 p1 = __ldg(&ce[j + 1]);
        float n0 = __int_as_float(p0.y), n1 = __int_as_float(p1.y);
        float2 v0 = *(const float2*)(h2 + (size_t)p0.x * 64 + lane * 2);
        float2 v1 = *(const float2*)(h2 + (size_t)p1.x * 64 + lane * 2);
        acc.x = fmaf(v0.x, n0, acc.x); acc.y = fmaf(v0.y, n0, acc.y);
        acc.x = fmaf(v1.x, n1, acc.x); acc.y = fmaf(v1.y, n1, acc.y);
    }
    if (j < e) {
        int2 p = __ldg(&ce[j]);
        float n = __int_as_float(p.y);
        float2 v = *(const float2*)(h2 + (size_t)p.x * 64 + lane * 2);
        acc.x = fmaf(v.x, n, acc.x); acc.y = fmaf(v.y, n, acc.y);
    }
    float2 bb = *(const float2*)(b2 + lane * 2);
    acc.x = fmaxf(acc.x + bb.x, 0.f);
    acc.y = fmaxf(acc.y + bb.y, 0.f);

    int gph = batch[node];
    atomicMax((unsigned int*)&pool[gph * H2 + lane * 2],     __float_as_uint(acc.x));
    atomicMax((unsigned int*)&pool[gph * H2 + lane * 2 + 1], __float_as_uint(acc.y));
}

// ---------------------------------------------------------------- final FC
__global__ void k_fc(const float* __restrict__ pool, const float* __restrict__ Wfc,
                     const float* __restrict__ bfc, float* __restrict__ out)
{
    __shared__ float w[H2 * OUT_DIM];
    __shared__ float bb[OUT_DIM];
    int tid = threadIdx.x;
    for (int i = tid; i < H2 * OUT_DIM; i += blockDim.x) w[i] = Wfc[i];
    if (tid < OUT_DIM) bb[tid] = bfc[tid];
    __syncthreads();
    if (tid < N_GRAPHS) {
        float acc[OUT_DIM];
#pragma unroll
        for (int j = 0; j < OUT_DIM; j++) acc[j] = bb[j];
        for (int k = 0; k < H2; k++) {
            float g = pool[tid * H2 + k];
#pragma unroll
            for (int j = 0; j < OUT_DIM; j++) acc[j] = fmaf(g, w[k * OUT_DIM + j], acc[j]);
        }
#pragma unroll
        for (int j = 0; j < OUT_DIM; j++) out[tid * OUT_DIM + j] = acc[j];
    }
}

// ---------------------------------------------------------------- launch
extern "C" void kernel_launch(void* const* d_in, const int* in_sizes, int n_in,
                              void* d_out, int out_size)
{
    const float* x    = (const float*)d_in[0];
    const int*   ei   = (const int*)d_in[1];
    const int*   batch= (const int*)d_in[2];
    const float* W1   = (const float*)d_in[3];
    const float* b1   = (const float*)d_in[4];
    const float* W2   = (const float*)d_in[5];
    const float* b2   = (const float*)d_in[6];
    const float* Wfc  = (const float*)d_in[7];
    const float* bfc  = (const float*)d_in[8];
    float* out = (float*)d_out;

    const int* row = ei;
    const int* col = ei + N_EDGES;

    int *deg, *off, *cursor;
    int2* cedge;
    float *dis, *h1, *h2, *pool;
    cudaGetSymbolAddress((void**)&deg,    g_deg);
    cudaGetSymbolAddress((void**)&off,    g_off);
    cudaGetSymbolAddress((void**)&cursor, g_cursor);
    cudaGetSymbolAddress((void**)&dis,    g_dis);
    cudaGetSymbolAddress((void**)&cedge,  g_cedge);
    cudaGetSymbolAddress((void**)&h1,     g_h1);
    cudaGetSymbolAddress((void**)&h2,     g_h2);
    cudaGetSymbolAddress((void**)&pool,   g_pool);

    constexpr int FUSED_SMEM = (128 * 132 + 128 * 72) * 4;   // 104448 B
    cudaFuncSetAttribute(k_gather_gemm2,
                         cudaFuncAttributeMaxDynamicSharedMemorySize, FUSED_SMEM);

    cudaStream_t s2;
    cudaStreamCreateWithFlags(&s2, cudaStreamNonBlocking);
    cudaEvent_t evF, evJ;
    cudaEventCreateWithFlags(&evF, cudaEventDisableTiming);
    cudaEventCreateWithFlags(&evJ, cudaEventDisableTiming);

    // fork: CSR build on s2
    cudaEventRecord(evF, 0);
    cudaStreamWaitEvent(s2, evF, 0);
    cudaMemsetAsync(deg, 0, N_NODES * sizeof(int), s2);
    k_count<<<(N_EDGES + 255) / 256, 256, 0, s2>>>(col, deg);
    k_scan<<<1, 1024, 0, s2>>>(deg, off, cursor, dis);
    k_fill<<<(N_EDGES + 255) / 256, 256, 0, s2>>>(row, col, dis, cursor, cedge);
    cudaEventRecord(evJ, s2);

    // main: zero pool, GEMM1
    cudaMemsetAsync(pool, 0, N_GRAPHS * H2 * sizeof(float), 0);
    k_gemm_ca<128, 128, 16, 8, 4, 32, 64>
        <<<(N_NODES + 127) / 128, 256>>>(x, W1, h1, N_NODES, IN_DIM);

    // join; fused gather1+GEMM2
    cudaStreamWaitEvent(0, evJ, 0);
    k_gather_gemm2<<<(N_NODES + 127) / 128, 256, FUSED_SMEM>>>(
        h1, W2, h2, off, cedge, dis, b1);

    // gather2 + pool, FC
    k_gather64pool<<<(N_NODES * 32 + 255) / 256, 256>>>(h2, off, cedge, dis, b2, batch, pool);
    k_fc<<<1, 128>>>(pool, Wfc, bfc, out);
}

// round 5
// speedup vs baseline: 1.1280x; 1.1280x over previous
#include <cuda_runtime.h>
#include <cuda_bf16.h>
#include <cstdint>

// ----------------------------------------------------------------------------
// GCN: agg1 = relu(Ahat (x@W1) + b1); h2 = agg1 @ W2;
//      pool = segment_max(relu(Ahat h2 + b2), batch); out = pool @ Wfc + bfc
// CSR build on side stream (overlaps GEMM1). GEMMs: tf32 mma (cvt.rna) +
// cp.async double buffer. Gathers: warp/node, unroll-4, bias+relu fused.
// gather2 fused with max-pool (atomicMax epilogue, values >= 0).
// ----------------------------------------------------------------------------

#define N_NODES 50000
#define N_EDGES 800000
#define N_GRAPHS 128
#define IN_DIM 256
#define H1 128
#define H2 64
#define OUT_DIM 10

__device__ int   g_deg[N_NODES];
__device__ int   g_off[N_NODES + 1];
__device__ int   g_cursor[N_NODES];
__device__ float g_dis[N_NODES];
__device__ int2  g_cedge[N_EDGES];          // (row, norm-bits)
__device__ float g_h1[(size_t)N_NODES * H1];
__device__ float g_agg1[(size_t)N_NODES * H1];
__device__ float g_h2[(size_t)N_NODES * H2];
__device__ float g_pool[N_GRAPHS * H2];

// ---------------------------------------------------------------- utils
__device__ __forceinline__ uint32_t f2tf(float x) {
    uint32_t u;
    asm("cvt.rna.tf32.f32 %0, %1;" : "=r"(u) : "f"(x));
    return u;
}

#define MMA_TF32(d, a, b)                                                     \
    asm volatile(                                                             \
        "mma.sync.aligned.m16n8k8.row.col.f32.tf32.tf32.f32 "                 \
        "{%0,%1,%2,%3},{%4,%5,%6,%7},{%8,%9},{%0,%1,%2,%3};"                  \
        : "+f"((d)[0]), "+f"((d)[1]), "+f"((d)[2]), "+f"((d)[3])              \
        : "r"((a)[0]), "r"((a)[1]), "r"((a)[2]), "r"((a)[3]),                 \
          "r"((b)[0]), "r"((b)[1]))

__device__ __forceinline__ void cp16(uint32_t saddr, const void* gaddr, int sz) {
    asm volatile("cp.async.cg.shared.global [%0], [%1], 16, %2;"
                 :: "r"(saddr), "l"(gaddr), "r"(sz));
}

// ---------------------------------------------------------------- CSR build
__global__ void k_count(const int* __restrict__ col, int* deg) {
    int e = blockIdx.x * blockDim.x + threadIdx.x;
    if (e < N_EDGES) atomicAdd(&deg[col[e]], 1);
}

__global__ void __launch_bounds__(1024)
k_scan(const int* __restrict__ deg, int* __restrict__ off,
       int* __restrict__ cursor, float* __restrict__ dis)
{
    __shared__ int sums[1024];
    const int t = threadIdx.x;
    const int CHUNK = (N_NODES + 1023) / 1024;
    int lo = t * CHUNK; if (lo > N_NODES) lo = N_NODES;
    int hi = lo + CHUNK; if (hi > N_NODES) hi = N_NODES;

    int s = 0;
    for (int i = lo; i < hi; i++) s += deg[i];
    sums[t] = s;
    __syncthreads();
    for (int d = 1; d < 1024; d <<= 1) {
        int v = (t >= d) ? sums[t - d] : 0;
        __syncthreads();
        sums[t] += v;
        __syncthreads();
    }
    int run = (t == 0) ? 0 : sums[t - 1];
    for (int i = lo; i < hi; i++) {
        off[i] = run;
        cursor[i] = run;
        int dg = deg[i];
        dis[i] = rsqrtf((float)(dg + 1));
        run += dg;
    }
    if (t == 1023) off[N_NODES] = run;
}

__global__ void k_fill(const int* __restrict__ row, const int* __restrict__ col,
                       const float* __restrict__ dis, int* cursor,
                       int2* __restrict__ cedge)
{
    int e = blockIdx.x * blockDim.x + threadIdx.x;
    if (e >= N_EDGES) return;
    int r = row[e], c = col[e];
    int p = atomicAdd(&cursor[c], 1);
    cedge[p] = make_int2(r, __float_as_int(dis[r] * dis[c]));
}

// ---------------------------------------------------------------- tf32 GEMM (cp.async dbuf)
template<int BM, int BN, int BK, int WARPS, int WARPS_M, int WM, int WN>
__global__ void __launch_bounds__(WARPS * 32)
k_gemm_ca(const float* __restrict__ A, const float* __restrict__ B,
          float* __restrict__ C, int M, int K)
{
    constexpr int MT = WM / 16, NT = WN / 8;
    constexpr int SA = BK + 4;
    constexpr int SB = BN + 8;
    __shared__ float As[2][BM * SA];
    __shared__ float Bs[2][BK * SB];

    const int tid = threadIdx.x, wid = tid >> 5, lane = tid & 31;
    const int wm = wid % WARPS_M, wn = wid / WARPS_M;
    const int g = lane >> 2, tig = lane & 3;
    const int m0 = blockIdx.x * BM;

    float acc[MT][NT][4];
#pragma unroll
    for (int i = 0; i < MT; i++)
#pragma unroll
        for (int j = 0; j < NT; j++)
#pragma unroll
            for (int q = 0; q < 4; q++) acc[i][j][q] = 0.f;

    auto loadTiles = [&](int buf, int k0) {
#pragma unroll
        for (int i = tid; i < BM * BK / 4; i += WARPS * 32) {
            int r = i / (BK / 4), c4 = i % (BK / 4);
            cp16((uint32_t)__cvta_generic_to_shared(&As[buf][r * SA + c4 * 4]),
                 A + (size_t)(m0 + r) * K + k0 + c4 * 4,
                 (m0 + r < M) ? 16 : 0);
        }
#pragma unroll
        for (int i = tid; i < BK * BN / 4; i += WARPS * 32) {
            int kk = i / (BN / 4), c4 = i % (BN / 4);
            cp16((uint32_t)__cvta_generic_to_shared(&Bs[buf][kk * SB + c4 * 4]),
                 B + (size_t)(k0 + kk) * BN + c4 * 4, 16);
        }
        asm volatile("cp.async.commit_group;");
    };

    const int nk = K / BK;
    loadTiles(0, 0);
    for (int t = 0; t < nk; t++) {
        if (t + 1 < nk) {
            loadTiles((t + 1) & 1, (t + 1) * BK);
            asm volatile("cp.async.wait_group 1;");
        } else {
            asm volatile("cp.async.wait_group 0;");
        }
        __syncthreads();
        const int buf = t & 1;

#pragma unroll
        for (int kk = 0; kk < BK / 8; kk++) {
            uint32_t af[MT][4], bf[NT][2];
#pragma unroll
            for (int mt = 0; mt < MT; mt++) {
                int r = wm * WM + mt * 16;
                af[mt][0] = f2tf(As[buf][(r + g)     * SA + kk * 8 + tig]);
                af[mt][1] = f2tf(As[buf][(r + g + 8) * SA + kk * 8 + tig]);
                af[mt][2] = f2tf(As[buf][(r + g)     * SA + kk * 8 + tig + 4]);
                af[mt][3] = f2tf(As[buf][(r + g + 8) * SA + kk * 8 + tig + 4]);
            }
#pragma unroll
            for (int nt = 0; nt < NT; nt++) {
                int c = wn * WN + nt * 8;
                bf[nt][0] = f2tf(Bs[buf][(kk * 8 + tig)     * SB + c + g]);
                bf[nt][1] = f2tf(Bs[buf][(kk * 8 + tig + 4) * SB + c + g]);
            }
#pragma unroll
            for (int mt = 0; mt < MT; mt++)
#pragma unroll
                for (int nt = 0; nt < NT; nt++)
                    MMA_TF32(acc[mt][nt], af[mt], bf[nt]);
        }
        __syncthreads();
    }

#pragma unroll
    for (int mt = 0; mt < MT; mt++) {
        int r0 = m0 + wm * WM + mt * 16 + g;
#pragma unroll
        for (int nt = 0; nt < NT; nt++) {
            int c = wn * WN + nt * 8 + 2 * tig;
            if (r0 < M)
                *(float2*)(C + (size_t)r0 * BN + c) =
                    make_float2(acc[mt][nt][0], acc[mt][nt][1]);
            if (r0 + 8 < M)
                *(float2*)(C + (size_t)(r0 + 8) * BN + c) =
                    make_float2(acc[mt][nt][2], acc[mt][nt][3]);
        }
    }
}

// ---------------------------------------------------------------- gather1 (+bias+relu)
__global__ void k_gather128(const float* __restrict__ h, float* __restrict__ agg,
                            const int* __restrict__ off, const int2* __restrict__ ce,
                            const float* __restrict__ dis, const float* __restrict__ bias)
{
    int node = (blockIdx.x * blockDim.x + threadIdx.x) >> 5;
    int lane = threadIdx.x & 31;
    if (node >= N_NODES) return;

    float d = dis[node];
    float dd = d * d;
    float4 acc = *(const float4*)(h + (size_t)node * 128 + lane * 4);
    acc.x *= dd; acc.y *= dd; acc.z *= dd; acc.w *= dd;

    int s = off[node], e = off[node + 1];
    int j = s;
    for (; j + 3 < e; j += 4) {
        int2 p0 = __ldg(&ce[j]);
        int2 p1 = __ldg(&ce[j + 1]);
        int2 p2 = __ldg(&ce[j + 2]);
        int2 p3 = __ldg(&ce[j + 3]);
        float4 v0 = *(const float4*)(h + (size_t)p0.x * 128 + lane * 4);
        float4 v1 = *(const float4*)(h + (size_t)p1.x * 128 + lane * 4);
        float4 v2 = *(const float4*)(h + (size_t)p2.x * 128 + lane * 4);
        float4 v3 = *(const float4*)(h + (size_t)p3.x * 128 + lane * 4);
        float n0 = __int_as_float(p0.y), n1 = __int_as_float(p1.y);
        float n2 = __int_as_float(p2.y), n3 = __int_as_float(p3.y);
        acc.x = fmaf(v0.x, n0, acc.x); acc.y = fmaf(v0.y, n0, acc.y);
        acc.z = fmaf(v0.z, n0, acc.z); acc.w = fmaf(v0.w, n0, acc.w);
        acc.x = fmaf(v1.x, n1, acc.x); acc.y = fmaf(v1.y, n1, acc.y);
        acc.z = fmaf(v1.z, n1, acc.z); acc.w = fmaf(v1.w, n1, acc.w);
        acc.x = fmaf(v2.x, n2, acc.x); acc.y = fmaf(v2.y, n2, acc.y);
        acc.z = fmaf(v2.z, n2, acc.z); acc.w = fmaf(v2.w, n2, acc.w);
        acc.x = fmaf(v3.x, n3, acc.x); acc.y = fmaf(v3.y, n3, acc.y);
        acc.z = fmaf(v3.z, n3, acc.z); acc.w = fmaf(v3.w, n3, acc.w);
    }
    for (; j < e; j++) {
        int2 p = __ldg(&ce[j]);
        float n = __int_as_float(p.y);
        float4 v = *(const float4*)(h + (size_t)p.x * 128 + lane * 4);
        acc.x = fmaf(v.x, n, acc.x); acc.y = fmaf(v.y, n, acc.y);
        acc.z = fmaf(v.z, n, acc.z); acc.w = fmaf(v.w, n, acc.w);
    }
    float4 bb = *(const float4*)(bias + lane * 4);
    acc.x = fmaxf(acc.x + bb.x, 0.f); acc.y = fmaxf(acc.y + bb.y, 0.f);
    acc.z = fmaxf(acc.z + bb.z, 0.f); acc.w = fmaxf(acc.w + bb.w, 0.f);
    *(float4*)(agg + (size_t)node * 128 + lane * 4) = acc;
}

// ---------------------------------------------------------------- gather2 + max-pool
__global__ void k_gather64pool(const float* __restrict__ h2,
                               const int* __restrict__ off, const int2* __restrict__ ce,
                               const float* __restrict__ dis, const float* __restrict__ b2,
                               const int* __restrict__ batch, float* __restrict__ pool)
{
    int node = (blockIdx.x * blockDim.x + threadIdx.x) >> 5;
    int lane = threadIdx.x & 31;
    if (node >= N_NODES) return;

    float d = dis[node];
    float dd = d * d;
    float2 acc = *(const float2*)(h2 + (size_t)node * 64 + lane * 2);
    acc.x *= dd; acc.y *= dd;

    int s = off[node], e = off[node + 1];
    int j = s;
    for (; j + 3 < e; j += 4) {
        int2 p0 = __ldg(&ce[j]);
        int2 p1 = __ldg(&ce[j + 1]);
        int2 p2 = __ldg(&ce[j + 2]);
        int2 p3 = __ldg(&ce[j + 3]);
        float2 v0 = *(const float2*)(h2 + (size_t)p0.x * 64 + lane * 2);
        float2 v1 = *(const float2*)(h2 + (size_t)p1.x * 64 + lane * 2);
        float2 v2 = *(const float2*)(h2 + (size_t)p2.x * 64 + lane * 2);
        float2 v3 = *(const float2*)(h2 + (size_t)p3.x * 64 + lane * 2);
        float n0 = __int_as_float(p0.y), n1 = __int_as_float(p1.y);
        float n2 = __int_as_float(p2.y), n3 = __int_as_float(p3.y);
        acc.x = fmaf(v0.x, n0, acc.x); acc.y = fmaf(v0.y, n0, acc.y);
        acc.x = fmaf(v1.x, n1, acc.x); acc.y = fmaf(v1.y, n1, acc.y);
        acc.x = fmaf(v2.x, n2, acc.x); acc.y = fmaf(v2.y, n2, acc.y);
        acc.x = fmaf(v3.x, n3, acc.x); acc.y = fmaf(v3.y, n3, acc.y);
    }
    for (; j < e; j++) {
        int2 p = __ldg(&ce[j]);
        float n = __int_as_float(p.y);
        float2 v = *(const float2*)(h2 + (size_t)p.x * 64 + lane * 2);
        acc.x = fmaf(v.x, n, acc.x); acc.y = fmaf(v.y, n, acc.y);
    }
    float2 bb = *(const float2*)(b2 + lane * 2);
    acc.x = fmaxf(acc.x + bb.x, 0.f);
    acc.y = fmaxf(acc.y + bb.y, 0.f);

    int gph = batch[node];
    atomicMax((unsigned int*)&pool[gph * H2 + lane * 2],     __float_as_uint(acc.x));
    atomicMax((unsigned int*)&pool[gph * H2 + lane * 2 + 1], __float_as_uint(acc.y));
}

// ---------------------------------------------------------------- final FC
__global__ void k_fc(const float* __restrict__ pool, const float* __restrict__ Wfc,
                     const float* __restrict__ bfc, float* __restrict__ out)
{
    __shared__ float w[H2 * OUT_DIM];
    __shared__ float bb[OUT_DIM];
    int tid = threadIdx.x;
    for (int i = tid; i < H2 * OUT_DIM; i += blockDim.x) w[i] = Wfc[i];
    if (tid < OUT_DIM) bb[tid] = bfc[tid];
    __syncthreads();
    if (tid < N_GRAPHS) {
        float acc[OUT_DIM];
#pragma unroll
        for (int j = 0; j < OUT_DIM; j++) acc[j] = bb[j];
        for (int k = 0; k < H2; k++) {
            float g = pool[tid * H2 + k];
#pragma unroll
            for (int j = 0; j < OUT_DIM; j++) acc[j] = fmaf(g, w[k * OUT_DIM + j], acc[j]);
        }
#pragma unroll
        for (int j = 0; j < OUT_DIM; j++) out[tid * OUT_DIM + j] = acc[j];
    }
}

// ---------------------------------------------------------------- launch
extern "C" void kernel_launch(void* const* d_in, const int* in_sizes, int n_in,
                              void* d_out, int out_size)
{
    const float* x    = (const float*)d_in[0];
    const int*   ei   = (const int*)d_in[1];
    const int*   batch= (const int*)d_in[2];
    const float* W1   = (const float*)d_in[3];
    const float* b1   = (const float*)d_in[4];
    const float* W2   = (const float*)d_in[5];
    const float* b2   = (const float*)d_in[6];
    const float* Wfc  = (const float*)d_in[7];
    const float* bfc  = (const float*)d_in[8];
    float* out = (float*)d_out;

    const int* row = ei;
    const int* col = ei + N_EDGES;

    int *deg, *off, *cursor;
    int2* cedge;
    float *dis, *h1, *agg1, *h2, *pool;
    cudaGetSymbolAddress((void**)&deg,    g_deg);
    cudaGetSymbolAddress((void**)&off,    g_off);
    cudaGetSymbolAddress((void**)&cursor, g_cursor);
    cudaGetSymbolAddress((void**)&dis,    g_dis);
    cudaGetSymbolAddress((void**)&cedge,  g_cedge);
    cudaGetSymbolAddress((void**)&h1,     g_h1);
    cudaGetSymbolAddress((void**)&agg1,   g_agg1);
    cudaGetSymbolAddress((void**)&h2,     g_h2);
    cudaGetSymbolAddress((void**)&pool,   g_pool);

    cudaStream_t s2;
    cudaStreamCreateWithFlags(&s2, cudaStreamNonBlocking);
    cudaEvent_t evF, evJ;
    cudaEventCreateWithFlags(&evF, cudaEventDisableTiming);
    cudaEventCreateWithFlags(&evJ, cudaEventDisableTiming);

    // fork: CSR build on s2
    cudaEventRecord(evF, 0);
    cudaStreamWaitEvent(s2, evF, 0);
    cudaMemsetAsync(deg, 0, N_NODES * sizeof(int), s2);
    k_count<<<(N_EDGES + 255) / 256, 256, 0, s2>>>(col, deg);
    k_scan<<<1, 1024, 0, s2>>>(deg, off, cursor, dis);
    k_fill<<<(N_EDGES + 255) / 256, 256, 0, s2>>>(row, col, dis, cursor, cedge);
    cudaEventRecord(evJ, s2);

    // main: zero pool, GEMM1
    cudaMemsetAsync(pool, 0, N_GRAPHS * H2 * sizeof(float), 0);
    k_gemm_ca<128, 128, 16, 8, 4, 32, 64>
        <<<(N_NODES + 127) / 128, 256>>>(x, W1, h1, N_NODES, IN_DIM);

    // join; gather1 (+b1+relu) -> agg1
    cudaStreamWaitEvent(0, evJ, 0);
    k_gather128<<<(N_NODES * 32 + 255) / 256, 256>>>(h1, agg1, off, cedge, dis, b1);

    // GEMM2: h2 = agg1 @ W2
    k_gemm_ca<128, 64, 16, 8, 4, 32, 32>
        <<<(N_NODES + 127) / 128, 256>>>(agg1, W2, h2, N_NODES, H1);

    // gather2 + pool, FC
    k_gather64pool<<<(N_NODES * 32 + 255) / 256, 256>>>(h2, off, cedge, dis, b2, batch, pool);
    k_fc<<<1, 128>>>(pool, Wfc, bfc, out);
}

// round 6
// speedup vs baseline: 1.4437x; 1.2799x over previous
#include <cuda_runtime.h>
#include <cuda_fp16.h>
#include <cstdint>

// ----------------------------------------------------------------------------
// GCN: agg1 = relu(Ahat (x@W1) + b1); h2 = agg1 @ W2;
//      pool = segment_max(relu(Ahat h2 + b2), batch); out = pool @ Wfc + bfc
// CSR build (coalesced 3-phase scan) on side stream, overlapped with GEMM1.
// GEMMs: tf32 mma (cvt.rna) + cp.async dbuf; h1/h2 stored fp16 (halves the
// gather L2 traffic). Gathers: warp/node, unroll-4, bias+relu fused; gather2
// fused with max-pool.
// ----------------------------------------------------------------------------

#define N_NODES 50000
#define N_EDGES 800000
#define N_GRAPHS 128
#define IN_DIM 256
#define H1 128
#define H2 64
#define OUT_DIM 10
#define NB_SCAN ((N_NODES + 255) / 256)    // 196

__device__ int    g_deg[N_NODES];
__device__ int    g_part[256];
__device__ int    g_off[N_NODES + 1];
__device__ int    g_cursor[N_NODES];
__device__ float  g_dis[N_NODES];
__device__ int2   g_cedge[N_EDGES];          // (row, norm-bits)
__device__ __half g_h1[(size_t)N_NODES * H1];
__device__ float  g_agg1[(size_t)N_NODES * H1];
__device__ __half g_h2[(size_t)N_NODES * H2];
__device__ float  g_pool[N_GRAPHS * H2];

// ---------------------------------------------------------------- utils
__device__ __forceinline__ uint32_t f2tf(float x) {
    uint32_t u;
    asm("cvt.rna.tf32.f32 %0, %1;" : "=r"(u) : "f"(x));
    return u;
}

#define MMA_TF32(d, a, b)                                                     \
    asm volatile(                                                             \
        "mma.sync.aligned.m16n8k8.row.col.f32.tf32.tf32.f32 "                 \
        "{%0,%1,%2,%3},{%4,%5,%6,%7},{%8,%9},{%0,%1,%2,%3};"                  \
        : "+f"((d)[0]), "+f"((d)[1]), "+f"((d)[2]), "+f"((d)[3])              \
        : "r"((a)[0]), "r"((a)[1]), "r"((a)[2]), "r"((a)[3]),                 \
          "r"((b)[0]), "r"((b)[1]))

__device__ __forceinline__ void cp16(uint32_t saddr, const void* gaddr, int sz) {
    asm volatile("cp.async.cg.shared.global [%0], [%1], 16, %2;"
                 :: "r"(saddr), "l"(gaddr), "r"(sz));
}

__device__ __forceinline__ float4 ldh4(const __half* p) {
    uint2 u = *(const uint2*)p;
    float2 a = __half22float2(*(__half2*)&u.x);
    float2 b = __half22float2(*(__half2*)&u.y);
    return make_float4(a.x, a.y, b.x, b.y);
}

// ---------------------------------------------------------------- CSR build
__global__ void k_count(const int* __restrict__ col, int* deg) {
    int e = blockIdx.x * blockDim.x + threadIdx.x;
    if (e < N_EDGES) atomicAdd(&deg[col[e]], 1);
}

// phase 1: per-block sums (coalesced)
__global__ void k_scan1(const int* __restrict__ deg, int* __restrict__ part) {
    __shared__ int sh[256];
    int i = blockIdx.x * 256 + threadIdx.x;
    int v = (i < N_NODES) ? deg[i] : 0;
    sh[threadIdx.x] = v;
    __syncthreads();
#pragma unroll
    for (int s = 128; s > 0; s >>= 1) {
        if (threadIdx.x < s) sh[threadIdx.x] += sh[threadIdx.x + s];
        __syncthreads();
    }
    if (threadIdx.x == 0) part[blockIdx.x] = sh[0];
}

// phase 2: exclusive scan of NB_SCAN partials (single block)
__global__ void k_scan2(int* part) {
    __shared__ int sh[256];
    int t = threadIdx.x;
    int v = (t < NB_SCAN) ? part[t] : 0;
    sh[t] = v;
    __syncthreads();
#pragma unroll
    for (int d = 1; d < 256; d <<= 1) {
        int u = (t >= d) ? sh[t - d] : 0;
        __syncthreads();
        sh[t] += u;
        __syncthreads();
    }
    if (t < NB_SCAN) part[t] = sh[t] - v;
}

// phase 3: per-block exclusive scan + apply; also dis = 1/sqrt(deg+1)
__global__ void k_scan3(const int* __restrict__ deg, const int* __restrict__ part,
                        int* __restrict__ off, int* __restrict__ cursor,
                        float* __restrict__ dis)
{
    __shared__ int sh[256];
    int t = threadIdx.x;
    int i = blockIdx.x * 256 + t;
    int v = (i < N_NODES) ? deg[i] : 0;
    sh[t] = v;
    __syncthreads();
#pragma unroll
    for (int d = 1; d < 256; d <<= 1) {
        int u = (t >= d) ? sh[t - d] : 0;
        __syncthreads();
        sh[t] += u;
        __syncthreads();
    }
    if (i < N_NODES) {
        int o = part[blockIdx.x] + sh[t] - v;
        off[i] = o;
        cursor[i] = o;
        dis[i] = rsqrtf((float)(v + 1));
    }
    if (i == 0) off[N_NODES] = N_EDGES;
}

__global__ void k_fill(const int* __restrict__ row, const int* __restrict__ col,
                       const float* __restrict__ dis, int* cursor,
                       int2* __restrict__ cedge)
{
    int e = blockIdx.x * blockDim.x + threadIdx.x;
    if (e >= N_EDGES) return;
    int r = row[e], c = col[e];
    int p = atomicAdd(&cursor[c], 1);
    cedge[p] = make_int2(r, __float_as_int(dis[r] * dis[c]));
}

// ---------------------------------------------------------------- tf32 GEMM (cp.async dbuf, fp16 out)
template<int BM, int BN, int BK, int WARPS, int WARPS_M, int WM, int WN>
__global__ void __launch_bounds__(WARPS * 32)
k_gemm_ca(const float* __restrict__ A, const float* __restrict__ B,
          __half* __restrict__ C, int M, int K)
{
    constexpr int MT = WM / 16, NT = WN / 8;
    constexpr int SA = BK + 4;
    constexpr int SB = BN + 8;
    __shared__ float As[2][BM * SA];
    __shared__ float Bs[2][BK * SB];

    const int tid = threadIdx.x, wid = tid >> 5, lane = tid & 31;
    const int wm = wid % WARPS_M, wn = wid / WARPS_M;
    const int g = lane >> 2, tig = lane & 3;
    const int m0 = blockIdx.x * BM;

    float acc[MT][NT][4];
#pragma unroll
    for (int i = 0; i < MT; i++)
#pragma unroll
        for (int j = 0; j < NT; j++)
#pragma unroll
            for (int q = 0; q < 4; q++) acc[i][j][q] = 0.f;

    auto loadTiles = [&](int buf, int k0) {
#pragma unroll
        for (int i = tid; i < BM * BK / 4; i += WARPS * 32) {
            int r = i / (BK / 4), c4 = i % (BK / 4);
            cp16((uint32_t)__cvta_generic_to_shared(&As[buf][r * SA + c4 * 4]),
                 A + (size_t)(m0 + r) * K + k0 + c4 * 4,
                 (m0 + r < M) ? 16 : 0);
        }
#pragma unroll
        for (int i = tid; i < BK * BN / 4; i += WARPS * 32) {
            int kk = i / (BN / 4), c4 = i % (BN / 4);
            cp16((uint32_t)__cvta_generic_to_shared(&Bs[buf][kk * SB + c4 * 4]),
                 B + (size_t)(k0 + kk) * BN + c4 * 4, 16);
        }
        asm volatile("cp.async.commit_group;");
    };

    const int nk = K / BK;
    loadTiles(0, 0);
    for (int t = 0; t < nk; t++) {
        if (t + 1 < nk) {
            loadTiles((t + 1) & 1, (t + 1) * BK);
            asm volatile("cp.async.wait_group 1;");
        } else {
            asm volatile("cp.async.wait_group 0;");
        }
        __syncthreads();
        const int buf = t & 1;

#pragma unroll
        for (int kk = 0; kk < BK / 8; kk++) {
            uint32_t af[MT][4], bf[NT][2];
#pragma unroll
            for (int mt = 0; mt < MT; mt++) {
                int r = wm * WM + mt * 16;
                af[mt][0] = f2tf(As[buf][(r + g)     * SA + kk * 8 + tig]);
                af[mt][1] = f2tf(As[buf][(r + g + 8) * SA + kk * 8 + tig]);
                af[mt][2] = f2tf(As[buf][(r + g)     * SA + kk * 8 + tig + 4]);
                af[mt][3] = f2tf(As[buf][(r + g + 8) * SA + kk * 8 + tig + 4]);
            }
#pragma unroll
            for (int nt = 0; nt < NT; nt++) {
                int c = wn * WN + nt * 8;
                bf[nt][0] = f2tf(Bs[buf][(kk * 8 + tig)     * SB + c + g]);
                bf[nt][1] = f2tf(Bs[buf][(kk * 8 + tig + 4) * SB + c + g]);
            }
#pragma unroll
            for (int mt = 0; mt < MT; mt++)
#pragma unroll
                for (int nt = 0; nt < NT; nt++)
                    MMA_TF32(acc[mt][nt], af[mt], bf[nt]);
        }
        __syncthreads();
    }

#pragma unroll
    for (int mt = 0; mt < MT; mt++) {
        int r0 = m0 + wm * WM + mt * 16 + g;
#pragma unroll
        for (int nt = 0; nt < NT; nt++) {
            int c = wn * WN + nt * 8 + 2 * tig;
            if (r0 < M)
                *(__half2*)(C + (size_t)r0 * BN + c) =
                    __floats2half2_rn(acc[mt][nt][0], acc[mt][nt][1]);
            if (r0 + 8 < M)
                *(__half2*)(C + (size_t)(r0 + 8) * BN + c) =
                    __floats2half2_rn(acc[mt][nt][2], acc[mt][nt][3]);
        }
    }
}

// ---------------------------------------------------------------- gather1 (+bias+relu), fp16 in / fp32 out
__global__ void k_gather128(const __half* __restrict__ h, float* __restrict__ agg,
                            const int* __restrict__ off, const int2* __restrict__ ce,
                            const float* __restrict__ dis, const float* __restrict__ bias)
{
    int node = (blockIdx.x * blockDim.x + threadIdx.x) >> 5;
    int lane = threadIdx.x & 31;
    if (node >= N_NODES) return;

    float d = dis[node];
    float dd = d * d;
    float4 acc = ldh4(h + (size_t)node * 128 + lane * 4);
    acc.x *= dd; acc.y *= dd; acc.z *= dd; acc.w *= dd;

    int s = off[node], e = off[node + 1];
    int j = s;
    for (; j + 3 < e; j += 4) {
        int2 p0 = __ldg(&ce[j]);
        int2 p1 = __ldg(&ce[j + 1]);
        int2 p2 = __ldg(&ce[j + 2]);
        int2 p3 = __ldg(&ce[j + 3]);
        float4 v0 = ldh4(h + (size_t)p0.x * 128 + lane * 4);
        float4 v1 = ldh4(h + (size_t)p1.x * 128 + lane * 4);
        float4 v2 = ldh4(h + (size_t)p2.x * 128 + lane * 4);
        float4 v3 = ldh4(h + (size_t)p3.x * 128 + lane * 4);
        float n0 = __int_as_float(p0.y), n1 = __int_as_float(p1.y);
        float n2 = __int_as_float(p2.y), n3 = __int_as_float(p3.y);
        acc.x = fmaf(v0.x, n0, acc.x); acc.y = fmaf(v0.y, n0, acc.y);
        acc.z = fmaf(v0.z, n0, acc.z); acc.w = fmaf(v0.w, n0, acc.w);
        acc.x = fmaf(v1.x, n1, acc.x); acc.y = fmaf(v1.y, n1, acc.y);
        acc.z = fmaf(v1.z, n1, acc.z); acc.w = fmaf(v1.w, n1, acc.w);
        acc.x = fmaf(v2.x, n2, acc.x); acc.y = fmaf(v2.y, n2, acc.y);
        acc.z = fmaf(v2.z, n2, acc.z); acc.w = fmaf(v2.w, n2, acc.w);
        acc.x = fmaf(v3.x, n3, acc.x); acc.y = fmaf(v3.y, n3, acc.y);
        acc.z = fmaf(v3.z, n3, acc.z); acc.w = fmaf(v3.w, n3, acc.w);
    }
    for (; j < e; j++) {
        int2 p = __ldg(&ce[j]);
        float n = __int_as_float(p.y);
        float4 v = ldh4(h + (size_t)p.x * 128 + lane * 4);
        acc.x = fmaf(v.x, n, acc.x); acc.y = fmaf(v.y, n, acc.y);
        acc.z = fmaf(v.z, n, acc.z); acc.w = fmaf(v.w, n, acc.w);
    }
    float4 bb = *(const float4*)(bias + lane * 4);
    acc.x = fmaxf(acc.x + bb.x, 0.f); acc.y = fmaxf(acc.y + bb.y, 0.f);
    acc.z = fmaxf(acc.z + bb.z, 0.f); acc.w = fmaxf(acc.w + bb.w, 0.f);
    *(float4*)(agg + (size_t)node * 128 + lane * 4) = acc;
}

// ---------------------------------------------------------------- gather2 + max-pool (fp16 in)
__global__ void k_gather64pool(const __half* __restrict__ h2,
                               const int* __restrict__ off, const int2* __restrict__ ce,
                               const float* __restrict__ dis, const float* __restrict__ b2,
                               const int* __restrict__ batch, float* __restrict__ pool)
{
    int node = (blockIdx.x * blockDim.x + threadIdx.x) >> 5;
    int lane = threadIdx.x & 31;
    if (node >= N_NODES) return;

    float d = dis[node];
    float dd = d * d;
    float2 acc = __half22float2(*(const __half2*)(h2 + (size_t)node * 64 + lane * 2));
    acc.x *= dd; acc.y *= dd;

    int s = off[node], e = off[node + 1];
    int j = s;
    for (; j + 3 < e; j += 4) {
        int2 p0 = __ldg(&ce[j]);
        int2 p1 = __ldg(&ce[j + 1]);
        int2 p2 = __ldg(&ce[j + 2]);
        int2 p3 = __ldg(&ce[j + 3]);
        float2 v0 = __half22float2(*(const __half2*)(h2 + (size_t)p0.x * 64 + lane * 2));
        float2 v1 = __half22float2(*(const __half2*)(h2 + (size_t)p1.x * 64 + lane * 2));
        float2 v2 = __half22float2(*(const __half2*)(h2 + (size_t)p2.x * 64 + lane * 2));
        float2 v3 = __half22float2(*(const __half2*)(h2 + (size_t)p3.x * 64 + lane * 2));
        float n0 = __int_as_float(p0.y), n1 = __int_as_float(p1.y);
        float n2 = __int_as_float(p2.y), n3 = __int_as_float(p3.y);
        acc.x = fmaf(v0.x, n0, acc.x); acc.y = fmaf(v0.y, n0, acc.y);
        acc.x = fmaf(v1.x, n1, acc.x); acc.y = fmaf(v1.y, n1, acc.y);
        acc.x = fmaf(v2.x, n2, acc.x); acc.y = fmaf(v2.y, n2, acc.y);
        acc.x = fmaf(v3.x, n3, acc.x); acc.y = fmaf(v3.y, n3, acc.y);
    }
    for (; j < e; j++) {
        int2 p = __ldg(&ce[j]);
        float n = __int_as_float(p.y);
        float2 v = __half22float2(*(const __half2*)(h2 + (size_t)p.x * 64 + lane * 2));
        acc.x = fmaf(v.x, n, acc.x); acc.y = fmaf(v.y, n, acc.y);
    }
    float2 bb = *(const float2*)(b2 + lane * 2);
    acc.x = fmaxf(acc.x + bb.x, 0.f);
    acc.y = fmaxf(acc.y + bb.y, 0.f);

    int gph = batch[node];
    atomicMax((unsigned int*)&pool[gph * H2 + lane * 2],     __float_as_uint(acc.x));
    atomicMax((unsigned int*)&pool[gph * H2 + lane * 2 + 1], __float_as_uint(acc.y));
}

// ---------------------------------------------------------------- final FC
__global__ void k_fc(const float* __restrict__ pool, const float* __restrict__ Wfc,
                     const float* __restrict__ bfc, float* __restrict__ out)
{
    __shared__ float w[H2 * OUT_DIM];
    __shared__ float bb[OUT_DIM];
    int tid = threadIdx.x;
    for (int i = tid; i < H2 * OUT_DIM; i += blockDim.x) w[i] = Wfc[i];
    if (tid < OUT_DIM) bb[tid] = bfc[tid];
    __syncthreads();
    if (tid < N_GRAPHS) {
        float acc[OUT_DIM];
#pragma unroll
        for (int j = 0; j < OUT_DIM; j++) acc[j] = bb[j];
        for (int k = 0; k < H2; k++) {
            float g = pool[tid * H2 + k];
#pragma unroll
            for (int j = 0; j < OUT_DIM; j++) acc[j] = fmaf(g, w[k * OUT_DIM + j], acc[j]);
        }
#pragma unroll
        for (int j = 0; j < OUT_DIM; j++) out[tid * OUT_DIM + j] = acc[j];
    }
}

// ---------------------------------------------------------------- launch
extern "C" void kernel_launch(void* const* d_in, const int* in_sizes, int n_in,
                              void* d_out, int out_size)
{
    const float* x    = (const float*)d_in[0];
    const int*   ei   = (const int*)d_in[1];
    const int*   batch= (const int*)d_in[2];
    const float* W1   = (const float*)d_in[3];
    const float* b1   = (const float*)d_in[4];
    const float* W2   = (const float*)d_in[5];
    const float* b2   = (const float*)d_in[6];
    const float* Wfc  = (const float*)d_in[7];
    const float* bfc  = (const float*)d_in[8];
    float* out = (float*)d_out;

    const int* row = ei;
    const int* col = ei + N_EDGES;

    int *deg, *part, *off, *cursor;
    int2* cedge;
    float *dis, *agg1, *pool;
    __half *h1, *h2;
    cudaGetSymbolAddress((void**)&deg,    g_deg);
    cudaGetSymbolAddress((void**)&part,   g_part);
    cudaGetSymbolAddress((void**)&off,    g_off);
    cudaGetSymbolAddress((void**)&cursor, g_cursor);
    cudaGetSymbolAddress((void**)&dis,    g_dis);
    cudaGetSymbolAddress((void**)&cedge,  g_cedge);
    cudaGetSymbolAddress((void**)&h1,     g_h1);
    cudaGetSymbolAddress((void**)&agg1,   g_agg1);
    cudaGetSymbolAddress((void**)&h2,     g_h2);
    cudaGetSymbolAddress((void**)&pool,   g_pool);

    cudaStream_t s2;
    cudaStreamCreateWithFlags(&s2, cudaStreamNonBlocking);
    cudaEvent_t evF, evJ;
    cudaEventCreateWithFlags(&evF, cudaEventDisableTiming);
    cudaEventCreateWithFlags(&evJ, cudaEventDisableTiming);

    // fork: CSR build + pool zero on s2
    cudaEventRecord(evF, 0);
    cudaStreamWaitEvent(s2, evF, 0);
    cudaMemsetAsync(deg, 0, N_NODES * sizeof(int), s2);
    cudaMemsetAsync(pool, 0, N_GRAPHS * H2 * sizeof(float), s2);
    k_count<<<(N_EDGES + 255) / 256, 256, 0, s2>>>(col, deg);
    k_scan1<<<NB_SCAN, 256, 0, s2>>>(deg, part);
    k_scan2<<<1, 256, 0, s2>>>(part);
    k_scan3<<<NB_SCAN, 256, 0, s2>>>(deg, part, off, cursor, dis);
    k_fill<<<(N_EDGES + 255) / 256, 256, 0, s2>>>(row, col, dis, cursor, cedge);
    cudaEventRecord(evJ, s2);

    // main: GEMM1 (h1 fp16 out)
    k_gemm_ca<128, 128, 16, 8, 4, 32, 64>
        <<<(N_NODES + 127) / 128, 256>>>(x, W1, h1, N_NODES, IN_DIM);

    // join; gather1 (+b1+relu) -> agg1 (fp32)
    cudaStreamWaitEvent(0, evJ, 0);
    k_gather128<<<(N_NODES * 32 + 255) / 256, 256>>>(h1, agg1, off, cedge, dis, b1);

    // GEMM2: h2 = agg1 @ W2 (fp16 out)
    k_gemm_ca<128, 64, 16, 8, 4, 32, 32>
        <<<(N_NODES + 127) / 128, 256>>>(agg1, W2, h2, N_NODES, H1);

    // gather2 + pool, FC
    k_gather64pool<<<(N_NODES * 32 + 255) / 256, 256>>>(h2, off, cedge, dis, b2, batch, pool);
    k_fc<<<1, 128>>>(pool, Wfc, bfc, out);
}

// round 7
// speedup vs baseline: 2.0246x; 1.4023x over previous
#include <cuda_runtime.h>
#include <cuda_fp16.h>
#include <cstdint>

// ----------------------------------------------------------------------------
// GCN: agg1 = relu(Ahat (x@W1) + b1); h2 = agg1 @ W2;
//      pool = segment_max(relu(Ahat h2 + b2), batch); out = pool @ Wfc + bfc
// GEMM1: tf32 mma, 512-thr blocks (32x32 warp tiles, high occ), cp.async dbuf.
// GEMM2: fp16 mma m16n8k16, whole K=128 in smem, agg1 stored fp16.
// CSR build (ILP-4 count/fill, 3-phase scan) on side stream under GEMM1.
// Gathers: warp/node, unroll-4, bias+relu fused; gather2 fused with max-pool.
// ----------------------------------------------------------------------------

#define N_NODES 50000
#define N_EDGES 800000
#define N_GRAPHS 128
#define IN_DIM 256
#define H1 128
#define H2 64
#define OUT_DIM 10
#define NB_SCAN ((N_NODES + 255) / 256)    // 196

__device__ int    g_deg[N_NODES];
__device__ int    g_part[256];
__device__ int    g_off[N_NODES + 1];
__device__ int    g_cursor[N_NODES];
__device__ float  g_dis[N_NODES];
__device__ int2   g_cedge[N_EDGES];          // (row, norm-bits)
__device__ __half g_h1[(size_t)N_NODES * H1];
__device__ __half g_agg1[(size_t)N_NODES * H1];
__device__ __half g_h2[(size_t)N_NODES * H2];
__device__ float  g_pool[N_GRAPHS * H2];

// ---------------------------------------------------------------- utils
__device__ __forceinline__ uint32_t f2tf(float x) {
    uint32_t u;
    asm("cvt.rna.tf32.f32 %0, %1;" : "=r"(u) : "f"(x));
    return u;
}

#define MMA_TF32(d, a, b)                                                     \
    asm volatile(                                                             \
        "mma.sync.aligned.m16n8k8.row.col.f32.tf32.tf32.f32 "                 \
        "{%0,%1,%2,%3},{%4,%5,%6,%7},{%8,%9},{%0,%1,%2,%3};"                  \
        : "+f"((d)[0]), "+f"((d)[1]), "+f"((d)[2]), "+f"((d)[3])              \
        : "r"((a)[0]), "r"((a)[1]), "r"((a)[2]), "r"((a)[3]),                 \
          "r"((b)[0]), "r"((b)[1]))

#define MMA_F16(d, a, b)                                                      \
    asm volatile(                                                             \
        "mma.sync.aligned.m16n8k16.row.col.f32.f16.f16.f32 "                  \
        "{%0,%1,%2,%3},{%4,%5,%6,%7},{%8,%9},{%0,%1,%2,%3};"                  \
        : "+f"((d)[0]), "+f"((d)[1]), "+f"((d)[2]), "+f"((d)[3])              \
        : "r"((a)[0]), "r"((a)[1]), "r"((a)[2]), "r"((a)[3]),                 \
          "r"((b)[0]), "r"((b)[1]))

__device__ __forceinline__ void cp16(uint32_t saddr, const void* gaddr, int sz) {
    asm volatile("cp.async.cg.shared.global [%0], [%1], 16, %2;"
                 :: "r"(saddr), "l"(gaddr), "r"(sz));
}

__device__ __forceinline__ float4 ldh4(const __half* p) {
    uint2 u = *(const uint2*)p;
    float2 a = __half22float2(*(__half2*)&u.x);
    float2 b = __half22float2(*(__half2*)&u.y);
    return make_float4(a.x, a.y, b.x, b.y);
}

// ---------------------------------------------------------------- CSR build
__global__ void k_count(const int* __restrict__ col, int* deg) {
    int i = blockIdx.x * blockDim.x + threadIdx.x;
    if (i * 4 < N_EDGES) {
        int4 c = *(const int4*)(col + i * 4);
        atomicAdd(&deg[c.x], 1);
        atomicAdd(&deg[c.y], 1);
        atomicAdd(&deg[c.z], 1);
        atomicAdd(&deg[c.w], 1);
    }
}

__global__ void k_scan1(const int* __restrict__ deg, int* __restrict__ part) {
    __shared__ int sh[256];
    int i = blockIdx.x * 256 + threadIdx.x;
    int v = (i < N_NODES) ? deg[i] : 0;
    sh[threadIdx.x] = v;
    __syncthreads();
#pragma unroll
    for (int s = 128; s > 0; s >>= 1) {
        if (threadIdx.x < s) sh[threadIdx.x] += sh[threadIdx.x + s];
        __syncthreads();
    }
    if (threadIdx.x == 0) part[blockIdx.x] = sh[0];
}

__global__ void k_scan2(int* part) {
    __shared__ int sh[256];
    int t = threadIdx.x;
    int v = (t < NB_SCAN) ? part[t] : 0;
    sh[t] = v;
    __syncthreads();
#pragma unroll
    for (int d = 1; d < 256; d <<= 1) {
        int u = (t >= d) ? sh[t - d] : 0;
        __syncthreads();
        sh[t] += u;
        __syncthreads();
    }
    if (t < NB_SCAN) part[t] = sh[t] - v;
}

__global__ void k_scan3(const int* __restrict__ deg, const int* __restrict__ part,
                        int* __restrict__ off, int* __restrict__ cursor,
                        float* __restrict__ dis)
{
    __shared__ int sh[256];
    int t = threadIdx.x;
    int i = blockIdx.x * 256 + t;
    int v = (i < N_NODES) ? deg[i] : 0;
    sh[t] = v;
    __syncthreads();
#pragma unroll
    for (int d = 1; d < 256; d <<= 1) {
        int u = (t >= d) ? sh[t - d] : 0;
        __syncthreads();
        sh[t] += u;
        __syncthreads();
    }
    if (i < N_NODES) {
        int o = part[blockIdx.x] + sh[t] - v;
        off[i] = o;
        cursor[i] = o;
        dis[i] = rsqrtf((float)(v + 1));
    }
    if (i == 0) off[N_NODES] = N_EDGES;
}

__global__ void k_fill(const int* __restrict__ row, const int* __restrict__ col,
                       const float* __restrict__ dis, int* cursor,
                       int2* __restrict__ cedge)
{
    int i = blockIdx.x * blockDim.x + threadIdx.x;
    if (i * 4 >= N_EDGES) return;
    int4 r = *(const int4*)(row + i * 4);
    int4 c = *(const int4*)(col + i * 4);
    int p0 = atomicAdd(&cursor[c.x], 1);
    int p1 = atomicAdd(&cursor[c.y], 1);
    int p2 = atomicAdd(&cursor[c.z], 1);
    int p3 = atomicAdd(&cursor[c.w], 1);
    cedge[p0] = make_int2(r.x, __float_as_int(dis[r.x] * dis[c.x]));
    cedge[p1] = make_int2(r.y, __float_as_int(dis[r.y] * dis[c.y]));
    cedge[p2] = make_int2(r.z, __float_as_int(dis[r.z] * dis[c.z]));
    cedge[p3] = make_int2(r.w, __float_as_int(dis[r.w] * dis[c.w]));
}

// ---------------------------------------------------------------- GEMM1 (tf32, cp.async dbuf, fp16 out)
// 512 threads, 16 warps, warp tile 32x32 -> low regs, high occ.
template<int BM, int BN, int BK, int WARPS, int WARPS_M, int WM, int WN>
__global__ void __launch_bounds__(WARPS * 32)
k_gemm_ca(const float* __restrict__ A, const float* __restrict__ B,
          __half* __restrict__ C, int M, int K)
{
    constexpr int MT = WM / 16, NT = WN / 8;
    constexpr int SA = BK + 4;
    constexpr int SB = BN + 8;
    __shared__ float As[2][BM * SA];
    __shared__ float Bs[2][BK * SB];

    const int tid = threadIdx.x, wid = tid >> 5, lane = tid & 31;
    const int wm = wid % WARPS_M, wn = wid / WARPS_M;
    const int g = lane >> 2, tig = lane & 3;
    const int m0 = blockIdx.x * BM;

    float acc[MT][NT][4];
#pragma unroll
    for (int i = 0; i < MT; i++)
#pragma unroll
        for (int j = 0; j < NT; j++)
#pragma unroll
            for (int q = 0; q < 4; q++) acc[i][j][q] = 0.f;

    auto loadTiles = [&](int buf, int k0) {
#pragma unroll
        for (int i = tid; i < BM * BK / 4; i += WARPS * 32) {
            int r = i / (BK / 4), c4 = i % (BK / 4);
            cp16((uint32_t)__cvta_generic_to_shared(&As[buf][r * SA + c4 * 4]),
                 A + (size_t)(m0 + r) * K + k0 + c4 * 4,
                 (m0 + r < M) ? 16 : 0);
        }
#pragma unroll
        for (int i = tid; i < BK * BN / 4; i += WARPS * 32) {
            int kk = i / (BN / 4), c4 = i % (BN / 4);
            cp16((uint32_t)__cvta_generic_to_shared(&Bs[buf][kk * SB + c4 * 4]),
                 B + (size_t)(k0 + kk) * BN + c4 * 4, 16);
        }
        asm volatile("cp.async.commit_group;");
    };

    const int nk = K / BK;
    loadTiles(0, 0);
    for (int t = 0; t < nk; t++) {
        if (t + 1 < nk) {
            loadTiles((t + 1) & 1, (t + 1) * BK);
            asm volatile("cp.async.wait_group 1;");
        } else {
            asm volatile("cp.async.wait_group 0;");
        }
        __syncthreads();
        const int buf = t & 1;

#pragma unroll
        for (int kk = 0; kk < BK / 8; kk++) {
            uint32_t af[MT][4], bf[NT][2];
#pragma unroll
            for (int mt = 0; mt < MT; mt++) {
                int r = wm * WM + mt * 16;
                af[mt][0] = f2tf(As[buf][(r + g)     * SA + kk * 8 + tig]);
                af[mt][1] = f2tf(As[buf][(r + g + 8) * SA + kk * 8 + tig]);
                af[mt][2] = f2tf(As[buf][(r + g)     * SA + kk * 8 + tig + 4]);
                af[mt][3] = f2tf(As[buf][(r + g + 8) * SA + kk * 8 + tig + 4]);
            }
#pragma unroll
            for (int nt = 0; nt < NT; nt++) {
                int c = wn * WN + nt * 8;
                bf[nt][0] = f2tf(Bs[buf][(kk * 8 + tig)     * SB + c + g]);
                bf[nt][1] = f2tf(Bs[buf][(kk * 8 + tig + 4) * SB + c + g]);
            }
#pragma unroll
            for (int mt = 0; mt < MT; mt++)
#pragma unroll
                for (int nt = 0; nt < NT; nt++)
                    MMA_TF32(acc[mt][nt], af[mt], bf[nt]);
        }
        __syncthreads();
    }

#pragma unroll
    for (int mt = 0; mt < MT; mt++) {
        int r0 = m0 + wm * WM + mt * 16 + g;
#pragma unroll
        for (int nt = 0; nt < NT; nt++) {
            int c = wn * WN + nt * 8 + 2 * tig;
            if (r0 < M)
                *(__half2*)(C + (size_t)r0 * BN + c) =
                    __floats2half2_rn(acc[mt][nt][0], acc[mt][nt][1]);
            if (r0 + 8 < M)
                *(__half2*)(C + (size_t)(r0 + 8) * BN + c) =
                    __floats2half2_rn(acc[mt][nt][2], acc[mt][nt][3]);
        }
    }
}

// ---------------------------------------------------------------- GEMM2 (fp16 mma, K=128 single tile)
// h2[M,64] = agg1[M,128] @ W2[128,64].  256 threads, 8 warps, warp tile 32x32.
#define G2_SA 136   // halves per A row (128 + 8)
#define G2_SB 136   // halves per B (transposed) row
#define G2_SMEM ((128 * G2_SA + 64 * G2_SB) * 2)

__global__ void __launch_bounds__(256)
k_gemm2_f16(const __half* __restrict__ A, const float* __restrict__ W2,
            __half* __restrict__ C, int M)
{
    extern __shared__ __half sm[];
    __half* As  = sm;                     // [128][G2_SA]
    __half* Bs2 = sm + 128 * G2_SA;       // [64][G2_SB]  (n-major, k contiguous)

    const int tid = threadIdx.x, wid = tid >> 5, lane = tid & 31;
    const int wm = wid % 4, wn = wid / 4;            // wn 0..1
    const int g = lane >> 2, tig = lane & 3;
    const int m0 = blockIdx.x * 128;

    // A tile: 128 rows x 128 halves = 128 x 16 chunks of 16B
#pragma unroll
    for (int i = tid; i < 128 * 16; i += 256) {
        int r = i / 16, c8 = i % 16;
        cp16((uint32_t)__cvta_generic_to_shared(&As[r * G2_SA + c8 * 8]),
             A + (size_t)(m0 + r) * 128 + c8 * 8,
             (m0 + r < M) ? 16 : 0);
    }
    asm volatile("cp.async.commit_group;");

    // B: convert fp32 W2[k][n] -> fp16 Bs2[n][k]
#pragma unroll
    for (int i = tid; i < 128 * 64; i += 256) {
        int k = i >> 6, n = i & 63;
        Bs2[n * G2_SB + k] = __float2half(W2[i]);
    }
    asm volatile("cp.async.wait_group 0;");
    __syncthreads();

    float acc[2][4][4];
#pragma unroll
    for (int i = 0; i < 2; i++)
#pragma unroll
        for (int j = 0; j < 4; j++)
#pragma unroll
            for (int q = 0; q < 4; q++) acc[i][j][q] = 0.f;

#pragma unroll
    for (int kk = 0; kk < 8; kk++) {           // 8 x k16
        uint32_t af[2][4], bf[4][2];
#pragma unroll
        for (int mt = 0; mt < 2; mt++) {
            int r = wm * 32 + mt * 16;
            af[mt][0] = *(const uint32_t*)&As[(r + g)     * G2_SA + kk * 16 + 2 * tig];
            af[mt][1] = *(const uint32_t*)&As[(r + g + 8) * G2_SA + kk * 16 + 2 * tig];
            af[mt][2] = *(const uint32_t*)&As[(r + g)     * G2_SA + kk * 16 + 8 + 2 * tig];
            af[mt][3] = *(const uint32_t*)&As[(r + g + 8) * G2_SA + kk * 16 + 8 + 2 * tig];
        }
#pragma unroll
        for (int nt = 0; nt < 4; nt++) {
            int c = wn * 32 + nt * 8;
            bf[nt][0] = *(const uint32_t*)&Bs2[(c + g) * G2_SB + kk * 16 + 2 * tig];
            bf[nt][1] = *(const uint32_t*)&Bs2[(c + g) * G2_SB + kk * 16 + 8 + 2 * tig];
        }
#pragma unroll
        for (int mt = 0; mt < 2; mt++)
#pragma unroll
            for (int nt = 0; nt < 4; nt++)
                MMA_F16(acc[mt][nt], af[mt], bf[nt]);
    }

#pragma unroll
    for (int mt = 0; mt < 2; mt++) {
        int r0 = m0 + wm * 32 + mt * 16 + g;
#pragma unroll
        for (int nt = 0; nt < 4; nt++) {
            int c = wn * 32 + nt * 8 + 2 * tig;
            if (r0 < M)
                *(__half2*)(C + (size_t)r0 * 64 + c) =
                    __floats2half2_rn(acc[mt][nt][0], acc[mt][nt][1]);
            if (r0 + 8 < M)
                *(__half2*)(C + (size_t)(r0 + 8) * 64 + c) =
                    __floats2half2_rn(acc[mt][nt][2], acc[mt][nt][3]);
        }
    }
}

// ---------------------------------------------------------------- gather1 (+bias+relu), fp16 in/out
__global__ void k_gather128(const __half* __restrict__ h, __half* __restrict__ agg,
                            const int* __restrict__ off, const int2* __restrict__ ce,
                            const float* __restrict__ dis, const float* __restrict__ bias)
{
    int node = (blockIdx.x * blockDim.x + threadIdx.x) >> 5;
    int lane = threadIdx.x & 31;
    if (node >= N_NODES) return;

    float d = dis[node];
    float dd = d * d;
    float4 acc = ldh4(h + (size_t)node * 128 + lane * 4);
    acc.x *= dd; acc.y *= dd; acc.z *= dd; acc.w *= dd;

    int s = off[node], e = off[node + 1];
    int j = s;
    for (; j + 3 < e; j += 4) {
        int2 p0 = __ldg(&ce[j]);
        int2 p1 = __ldg(&ce[j + 1]);
        int2 p2 = __ldg(&ce[j + 2]);
        int2 p3 = __ldg(&ce[j + 3]);
        float4 v0 = ldh4(h + (size_t)p0.x * 128 + lane * 4);
        float4 v1 = ldh4(h + (size_t)p1.x * 128 + lane * 4);
        float4 v2 = ldh4(h + (size_t)p2.x * 128 + lane * 4);
        float4 v3 = ldh4(h + (size_t)p3.x * 128 + lane * 4);
        float n0 = __int_as_float(p0.y), n1 = __int_as_float(p1.y);
        float n2 = __int_as_float(p2.y), n3 = __int_as_float(p3.y);
        acc.x = fmaf(v0.x, n0, acc.x); acc.y = fmaf(v0.y, n0, acc.y);
        acc.z = fmaf(v0.z, n0, acc.z); acc.w = fmaf(v0.w, n0, acc.w);
        acc.x = fmaf(v1.x, n1, acc.x); acc.y = fmaf(v1.y, n1, acc.y);
        acc.z = fmaf(v1.z, n1, acc.z); acc.w = fmaf(v1.w, n1, acc.w);
        acc.x = fmaf(v2.x, n2, acc.x); acc.y = fmaf(v2.y, n2, acc.y);
        acc.z = fmaf(v2.z, n2, acc.z); acc.w = fmaf(v2.w, n2, acc.w);
        acc.x = fmaf(v3.x, n3, acc.x); acc.y = fmaf(v3.y, n3, acc.y);
        acc.z = fmaf(v3.z, n3, acc.z); acc.w = fmaf(v3.w, n3, acc.w);
    }
    for (; j < e; j++) {
        int2 p = __ldg(&ce[j]);
        float n = __int_as_float(p.y);
        float4 v = ldh4(h + (size_t)p.x * 128 + lane * 4);
        acc.x = fmaf(v.x, n, acc.x); acc.y = fmaf(v.y, n, acc.y);
        acc.z = fmaf(v.z, n, acc.z); acc.w = fmaf(v.w, n, acc.w);
    }
    float4 bb = *(const float4*)(bias + lane * 4);
    acc.x = fmaxf(acc.x + bb.x, 0.f); acc.y = fmaxf(acc.y + bb.y, 0.f);
    acc.z = fmaxf(acc.z + bb.z, 0.f); acc.w = fmaxf(acc.w + bb.w, 0.f);
    uint2 st;
    *(__half2*)&st.x = __floats2half2_rn(acc.x, acc.y);
    *(__half2*)&st.y = __floats2half2_rn(acc.z, acc.w);
    *(uint2*)(agg + (size_t)node * 128 + lane * 4) = st;
}

// ---------------------------------------------------------------- gather2 + max-pool (fp16 in)
__global__ void k_gather64pool(const __half* __restrict__ h2,
                               const int* __restrict__ off, const int2* __restrict__ ce,
                               const float* __restrict__ dis, const float* __restrict__ b2,
                               const int* __restrict__ batch, float* __restrict__ pool)
{
    int node = (blockIdx.x * blockDim.x + threadIdx.x) >> 5;
    int lane = threadIdx.x & 31;
    if (node >= N_NODES) return;

    float d = dis[node];
    float dd = d * d;
    float2 acc = __half22float2(*(const __half2*)(h2 + (size_t)node * 64 + lane * 2));
    acc.x *= dd; acc.y *= dd;

    int s = off[node], e = off[node + 1];
    int j = s;
    for (; j + 3 < e; j += 4) {
        int2 p0 = __ldg(&ce[j]);
        int2 p1 = __ldg(&ce[j + 1]);
        int2 p2 = __ldg(&ce[j + 2]);
        int2 p3 = __ldg(&ce[j + 3]);
        float2 v0 = __half22float2(*(const __half2*)(h2 + (size_t)p0.x * 64 + lane * 2));
        float2 v1 = __half22float2(*(const __half2*)(h2 + (size_t)p1.x * 64 + lane * 2));
        float2 v2 = __half22float2(*(const __half2*)(h2 + (size_t)p2.x * 64 + lane * 2));
        float2 v3 = __half22float2(*(const __half2*)(h2 + (size_t)p3.x * 64 + lane * 2));
        float n0 = __int_as_float(p0.y), n1 = __int_as_float(p1.y);
        float n2 = __int_as_float(p2.y), n3 = __int_as_float(p3.y);
        acc.x = fmaf(v0.x, n0, acc.x); acc.y = fmaf(v0.y, n0, acc.y);
        acc.x = fmaf(v1.x, n1, acc.x); acc.y = fmaf(v1.y, n1, acc.y);
        acc.x = fmaf(v2.x, n2, acc.x); acc.y = fmaf(v2.y, n2, acc.y);
        acc.x = fmaf(v3.x, n3, acc.x); acc.y = fmaf(v3.y, n3, acc.y);
    }
    for (; j < e; j++) {
        int2 p = __ldg(&ce[j]);
        float n = __int_as_float(p.y);
        float2 v = __half22float2(*(const __half2*)(h2 + (size_t)p.x * 64 + lane * 2));
        acc.x = fmaf(v.x, n, acc.x); acc.y = fmaf(v.y, n, acc.y);
    }
    float2 bb = *(const float2*)(b2 + lane * 2);
    acc.x = fmaxf(acc.x + bb.x, 0.f);
    acc.y = fmaxf(acc.y + bb.y, 0.f);

    int gph = batch[node];
    atomicMax((unsigned int*)&pool[gph * H2 + lane * 2],     __float_as_uint(acc.x));
    atomicMax((unsigned int*)&pool[gph * H2 + lane * 2 + 1], __float_as_uint(acc.y));
}

// ---------------------------------------------------------------- final FC
__global__ void k_fc(const float* __restrict__ pool, const float* __restrict__ Wfc,
                     const float* __restrict__ bfc, float* __restrict__ out)
{
    __shared__ float w[H2 * OUT_DIM];
    __shared__ float bb[OUT_DIM];
    int tid = threadIdx.x;
    for (int i = tid; i < H2 * OUT_DIM; i += blockDim.x) w[i] = Wfc[i];
    if (tid < OUT_DIM) bb[tid] = bfc[tid];
    __syncthreads();
    if (tid < N_GRAPHS) {
        float acc[OUT_DIM];
#pragma unroll
        for (int j = 0; j < OUT_DIM; j++) acc[j] = bb[j];
        for (int k = 0; k < H2; k++) {
            float g = pool[tid * H2 + k];
#pragma unroll
            for (int j = 0; j < OUT_DIM; j++) acc[j] = fmaf(g, w[k * OUT_DIM + j], acc[j]);
        }
#pragma unroll
        for (int j = 0; j < OUT_DIM; j++) out[tid * OUT_DIM + j] = acc[j];
    }
}

// ---------------------------------------------------------------- launch
extern "C" void kernel_launch(void* const* d_in, const int* in_sizes, int n_in,
                              void* d_out, int out_size)
{
    const float* x    = (const float*)d_in[0];
    const int*   ei   = (const int*)d_in[1];
    const int*   batch= (const int*)d_in[2];
    const float* W1   = (const float*)d_in[3];
    const float* b1   = (const float*)d_in[4];
    const float* W2   = (const float*)d_in[5];
    const float* b2   = (const float*)d_in[6];
    const float* Wfc  = (const float*)d_in[7];
    const float* bfc  = (const float*)d_in[8];
    float* out = (float*)d_out;

    const int* row = ei;
    const int* col = ei + N_EDGES;

    int *deg, *part, *off, *cursor;
    int2* cedge;
    float *dis, *pool;
    __half *h1, *agg1, *h2;
    cudaGetSymbolAddress((void**)&deg,    g_deg);
    cudaGetSymbolAddress((void**)&part,   g_part);
    cudaGetSymbolAddress((void**)&off,    g_off);
    cudaGetSymbolAddress((void**)&cursor, g_cursor);
    cudaGetSymbolAddress((void**)&dis,    g_dis);
    cudaGetSymbolAddress((void**)&cedge,  g_cedge);
    cudaGetSymbolAddress((void**)&h1,     g_h1);
    cudaGetSymbolAddress((void**)&agg1,   g_agg1);
    cudaGetSymbolAddress((void**)&h2,     g_h2);
    cudaGetSymbolAddress((void**)&pool,   g_pool);

    cudaFuncSetAttribute(k_gemm2_f16,
                         cudaFuncAttributeMaxDynamicSharedMemorySize, G2_SMEM);

    cudaStream_t s2;
    cudaStreamCreateWithFlags(&s2, cudaStreamNonBlocking);
    cudaEvent_t evF, evJ;
    cudaEventCreateWithFlags(&evF, cudaEventDisableTiming);
    cudaEventCreateWithFlags(&evJ, cudaEventDisableTiming);

    // fork: CSR build + pool zero on s2
    cudaEventRecord(evF, 0);
    cudaStreamWaitEvent(s2, evF, 0);
    cudaMemsetAsync(deg, 0, N_NODES * sizeof(int), s2);
    cudaMemsetAsync(pool, 0, N_GRAPHS * H2 * sizeof(float), s2);
    k_count<<<(N_EDGES / 4 + 255) / 256, 256, 0, s2>>>(col, deg);
    k_scan1<<<NB_SCAN, 256, 0, s2>>>(deg, part);
    k_scan2<<<1, 256, 0, s2>>>(part);
    k_scan3<<<NB_SCAN, 256, 0, s2>>>(deg, part, off, cursor, dis);
    k_fill<<<(N_EDGES / 4 + 255) / 256, 256, 0, s2>>>(row, col, dis, cursor, cedge);
    cudaEventRecord(evJ, s2);

    // main: GEMM1 (h1 fp16 out) — 512 threads, 32x32 warp tiles
    k_gemm_ca<128, 128, 16, 16, 4, 32, 32>
        <<<(N_NODES + 127) / 128, 512>>>(x, W1, h1, N_NODES, IN_DIM);

    // join; gather1 (+b1+relu) -> agg1 (fp16)
    cudaStreamWaitEvent(0, evJ, 0);
    k_gather128<<<(N_NODES * 32 + 255) / 256, 256>>>(h1, agg1, off, cedge, dis, b1);

    // GEMM2: h2 = agg1 @ W2 (fp16 mma)
    k_gemm2_f16<<<(N_NODES + 127) / 128, 256, G2_SMEM>>>(agg1, W2, h2, N_NODES);

    // gather2 + pool, FC
    k_gather64pool<<<(N_NODES * 32 + 255) / 256, 256>>>(h2, off, cedge, dis, b2, batch, pool);
    k_fc<<<1, 128>>>(pool, Wfc, bfc, out);
}

// round 8
// speedup vs baseline: 2.0358x; 1.0055x over previous
#include <cuda_runtime.h>
#include <cuda_fp16.h>
#include <cstdint>

// ----------------------------------------------------------------------------
// GCN: agg1 = relu(Ahat (x@W1) + b1); h2 = agg1 @ W2;
//      pool = segment_max(relu(Ahat h2 + b2), batch); out = pool @ Wfc + bfc
// GEMM1: tf32 mma, 512-thr blocks, 3-stage cp.async pipeline (dyn smem).
// GEMM2: fp16 mma m16n8k16, whole K=128 in smem, agg1 stored fp16.
// CSR build (ILP-4 count/fill, 3-phase scan) on side stream under GEMM1.
// Gathers: warp/node, unroll-8 (deep MLP), bias+relu fused; gather2+max-pool.
// ----------------------------------------------------------------------------

#define N_NODES 50000
#define N_EDGES 800000
#define N_GRAPHS 128
#define IN_DIM 256
#define H1 128
#define H2 64
#define OUT_DIM 10
#define NB_SCAN ((N_NODES + 255) / 256)    // 196

__device__ int    g_deg[N_NODES];
__device__ int    g_part[256];
__device__ int    g_off[N_NODES + 1];
__device__ int    g_cursor[N_NODES];
__device__ float  g_dis[N_NODES];
__device__ int2   g_cedge[N_EDGES];          // (row, norm-bits)
__device__ __half g_h1[(size_t)N_NODES * H1];
__device__ __half g_agg1[(size_t)N_NODES * H1];
__device__ __half g_h2[(size_t)N_NODES * H2];
__device__ float  g_pool[N_GRAPHS * H2];

// ---------------------------------------------------------------- utils
__device__ __forceinline__ uint32_t f2tf(float x) {
    uint32_t u;
    asm("cvt.rna.tf32.f32 %0, %1;" : "=r"(u) : "f"(x));
    return u;
}

#define MMA_TF32(d, a, b)                                                     \
    asm volatile(                                                             \
        "mma.sync.aligned.m16n8k8.row.col.f32.tf32.tf32.f32 "                 \
        "{%0,%1,%2,%3},{%4,%5,%6,%7},{%8,%9},{%0,%1,%2,%3};"                  \
        : "+f"((d)[0]), "+f"((d)[1]), "+f"((d)[2]), "+f"((d)[3])              \
        : "r"((a)[0]), "r"((a)[1]), "r"((a)[2]), "r"((a)[3]),                 \
          "r"((b)[0]), "r"((b)[1]))

#define MMA_F16(d, a, b)                                                      \
    asm volatile(                                                             \
        "mma.sync.aligned.m16n8k16.row.col.f32.f16.f16.f32 "                  \
        "{%0,%1,%2,%3},{%4,%5,%6,%7},{%8,%9},{%0,%1,%2,%3};"                  \
        : "+f"((d)[0]), "+f"((d)[1]), "+f"((d)[2]), "+f"((d)[3])              \
        : "r"((a)[0]), "r"((a)[1]), "r"((a)[2]), "r"((a)[3]),                 \
          "r"((b)[0]), "r"((b)[1]))

__device__ __forceinline__ void cp16(uint32_t saddr, const void* gaddr, int sz) {
    asm volatile("cp.async.cg.shared.global [%0], [%1], 16, %2;"
                 :: "r"(saddr), "l"(gaddr), "r"(sz));
}

__device__ __forceinline__ float4 ldh4(const __half* p) {
    uint2 u = *(const uint2*)p;
    float2 a = __half22float2(*(__half2*)&u.x);
    float2 b = __half22float2(*(__half2*)&u.y);
    return make_float4(a.x, a.y, b.x, b.y);
}

// ---------------------------------------------------------------- CSR build
__global__ void k_count(const int* __restrict__ col, int* deg) {
    int i = blockIdx.x * blockDim.x + threadIdx.x;
    if (i * 4 < N_EDGES) {
        int4 c = *(const int4*)(col + i * 4);
        atomicAdd(&deg[c.x], 1);
        atomicAdd(&deg[c.y], 1);
        atomicAdd(&deg[c.z], 1);
        atomicAdd(&deg[c.w], 1);
    }
}

__global__ void k_scan1(const int* __restrict__ deg, int* __restrict__ part) {
    __shared__ int sh[256];
    int i = blockIdx.x * 256 + threadIdx.x;
    int v = (i < N_NODES) ? deg[i] : 0;
    sh[threadIdx.x] = v;
    __syncthreads();
#pragma unroll
    for (int s = 128; s > 0; s >>= 1) {
        if (threadIdx.x < s) sh[threadIdx.x] += sh[threadIdx.x + s];
        __syncthreads();
    }
    if (threadIdx.x == 0) part[blockIdx.x] = sh[0];
}

__global__ void k_scan2(int* part) {
    __shared__ int sh[256];
    int t = threadIdx.x;
    int v = (t < NB_SCAN) ? part[t] : 0;
    sh[t] = v;
    __syncthreads();
#pragma unroll
    for (int d = 1; d < 256; d <<= 1) {
        int u = (t >= d) ? sh[t - d] : 0;
        __syncthreads();
        sh[t] += u;
        __syncthreads();
    }
    if (t < NB_SCAN) part[t] = sh[t] - v;
}

__global__ void k_scan3(const int* __restrict__ deg, const int* __restrict__ part,
                        int* __restrict__ off, int* __restrict__ cursor,
                        float* __restrict__ dis)
{
    __shared__ int sh[256];
    int t = threadIdx.x;
    int i = blockIdx.x * 256 + t;
    int v = (i < N_NODES) ? deg[i] : 0;
    sh[t] = v;
    __syncthreads();
#pragma unroll
    for (int d = 1; d < 256; d <<= 1) {
        int u = (t >= d) ? sh[t - d] : 0;
        __syncthreads();
        sh[t] += u;
        __syncthreads();
    }
    if (i < N_NODES) {
        int o = part[blockIdx.x] + sh[t] - v;
        off[i] = o;
        cursor[i] = o;
        dis[i] = rsqrtf((float)(v + 1));
    }
    if (i == 0) off[N_NODES] = N_EDGES;
}

__global__ void k_fill(const int* __restrict__ row, const int* __restrict__ col,
                       const float* __restrict__ dis, int* cursor,
                       int2* __restrict__ cedge)
{
    int i = blockIdx.x * blockDim.x + threadIdx.x;
    if (i * 4 >= N_EDGES) return;
    int4 r = *(const int4*)(row + i * 4);
    int4 c = *(const int4*)(col + i * 4);
    int p0 = atomicAdd(&cursor[c.x], 1);
    int p1 = atomicAdd(&cursor[c.y], 1);
    int p2 = atomicAdd(&cursor[c.z], 1);
    int p3 = atomicAdd(&cursor[c.w], 1);
    cedge[p0] = make_int2(r.x, __float_as_int(dis[r.x] * dis[c.x]));
    cedge[p1] = make_int2(r.y, __float_as_int(dis[r.y] * dis[c.y]));
    cedge[p2] = make_int2(r.z, __float_as_int(dis[r.z] * dis[c.z]));
    cedge[p3] = make_int2(r.w, __float_as_int(dis[r.w] * dis[c.w]));
}

// ---------------------------------------------------------------- GEMM1 (tf32, 3-stage cp.async, fp16 out)
template<int BM, int BN, int BK, int WARPS, int WARPS_M, int WM, int WN>
__global__ void __launch_bounds__(WARPS * 32)
k_gemm_ca(const float* __restrict__ A, const float* __restrict__ B,
          __half* __restrict__ C, int M, int K)
{
    constexpr int MT = WM / 16, NT = WN / 8;
    constexpr int SA = BK + 4;
    constexpr int SB = BN + 8;
    extern __shared__ float dyn[];
    float* As = dyn;                     // [3][BM*SA]
    float* Bs = dyn + 3 * BM * SA;       // [3][BK*SB]

    const int tid = threadIdx.x, wid = tid >> 5, lane = tid & 31;
    const int wm = wid % WARPS_M, wn = wid / WARPS_M;
    const int g = lane >> 2, tig = lane & 3;
    const int m0 = blockIdx.x * BM;

    float acc[MT][NT][4];
#pragma unroll
    for (int i = 0; i < MT; i++)
#pragma unroll
        for (int j = 0; j < NT; j++)
#pragma unroll
            for (int q = 0; q < 4; q++) acc[i][j][q] = 0.f;

    auto loadTiles = [&](int buf, int k0) {
        float* Ab = As + buf * BM * SA;
        float* Bb = Bs + buf * BK * SB;
#pragma unroll
        for (int i = tid; i < BM * BK / 4; i += WARPS * 32) {
            int r = i / (BK / 4), c4 = i % (BK / 4);
            cp16((uint32_t)__cvta_generic_to_shared(&Ab[r * SA + c4 * 4]),
                 A + (size_t)(m0 + r) * K + k0 + c4 * 4,
                 (m0 + r < M) ? 16 : 0);
        }
#pragma unroll
        for (int i = tid; i < BK * BN / 4; i += WARPS * 32) {
            int kk = i / (BN / 4), c4 = i % (BN / 4);
            cp16((uint32_t)__cvta_generic_to_shared(&Bb[kk * SB + c4 * 4]),
                 B + (size_t)(k0 + kk) * BN + c4 * 4, 16);
        }
        asm volatile("cp.async.commit_group;");
    };

    const int nk = K / BK;
    loadTiles(0, 0);
    loadTiles(1, BK);
    for (int t = 0; t < nk; t++) {
        if (t + 2 < nk) {
            loadTiles((t + 2) % 3, (t + 2) * BK);
            asm volatile("cp.async.wait_group 2;");
        } else if (t + 1 < nk) {
            asm volatile("cp.async.wait_group 1;");
        } else {
            asm volatile("cp.async.wait_group 0;");
        }
        __syncthreads();
        const int buf = t % 3;
        const float* Ab = As + buf * BM * SA;
        const float* Bb = Bs + buf * BK * SB;

#pragma unroll
        for (int kk = 0; kk < BK / 8; kk++) {
            uint32_t af[MT][4], bf[NT][2];
#pragma unroll
            for (int mt = 0; mt < MT; mt++) {
                int r = wm * WM + mt * 16;
                af[mt][0] = f2tf(Ab[(r + g)     * SA + kk * 8 + tig]);
                af[mt][1] = f2tf(Ab[(r + g + 8) * SA + kk * 8 + tig]);
                af[mt][2] = f2tf(Ab[(r + g)     * SA + kk * 8 + tig + 4]);
                af[mt][3] = f2tf(Ab[(r + g + 8) * SA + kk * 8 + tig + 4]);
            }
#pragma unroll
            for (int nt = 0; nt < NT; nt++) {
                int c = wn * WN + nt * 8;
                bf[nt][0] = f2tf(Bb[(kk * 8 + tig)     * SB + c + g]);
                bf[nt][1] = f2tf(Bb[(kk * 8 + tig + 4) * SB + c + g]);
            }
#pragma unroll
            for (int mt = 0; mt < MT; mt++)
#pragma unroll
                for (int nt = 0; nt < NT; nt++)
                    MMA_TF32(acc[mt][nt], af[mt], bf[nt]);
        }
        __syncthreads();
    }

#pragma unroll
    for (int mt = 0; mt < MT; mt++) {
        int r0 = m0 + wm * WM + mt * 16 + g;
#pragma unroll
        for (int nt = 0; nt < NT; nt++) {
            int c = wn * WN + nt * 8 + 2 * tig;
            if (r0 < M)
                *(__half2*)(C + (size_t)r0 * BN + c) =
                    __floats2half2_rn(acc[mt][nt][0], acc[mt][nt][1]);
            if (r0 + 8 < M)
                *(__half2*)(C + (size_t)(r0 + 8) * BN + c) =
                    __floats2half2_rn(acc[mt][nt][2], acc[mt][nt][3]);
        }
    }
}

#define G1_SMEM (3 * (128 * 20 + 16 * 136) * 4)

// ---------------------------------------------------------------- GEMM2 (fp16 mma, K=128 single tile)
#define G2_SA 136
#define G2_SB 136
#define G2_SMEM ((128 * G2_SA + 64 * G2_SB) * 2)

__global__ void __launch_bounds__(256)
k_gemm2_f16(const __half* __restrict__ A, const float* __restrict__ W2,
            __half* __restrict__ C, int M)
{
    extern __shared__ __half sm[];
    __half* As  = sm;                     // [128][G2_SA]
    __half* Bs2 = sm + 128 * G2_SA;       // [64][G2_SB]

    const int tid = threadIdx.x, wid = tid >> 5, lane = tid & 31;
    const int wm = wid % 4, wn = wid / 4;
    const int g = lane >> 2, tig = lane & 3;
    const int m0 = blockIdx.x * 128;

#pragma unroll
    for (int i = tid; i < 128 * 16; i += 256) {
        int r = i / 16, c8 = i % 16;
        cp16((uint32_t)__cvta_generic_to_shared(&As[r * G2_SA + c8 * 8]),
             A + (size_t)(m0 + r) * 128 + c8 * 8,
             (m0 + r < M) ? 16 : 0);
    }
    asm volatile("cp.async.commit_group;");

#pragma unroll
    for (int i = tid; i < 128 * 64; i += 256) {
        int k = i >> 6, n = i & 63;
        Bs2[n * G2_SB + k] = __float2half(W2[i]);
    }
    asm volatile("cp.async.wait_group 0;");
    __syncthreads();

    float acc[2][4][4];
#pragma unroll
    for (int i = 0; i < 2; i++)
#pragma unroll
        for (int j = 0; j < 4; j++)
#pragma unroll
            for (int q = 0; q < 4; q++) acc[i][j][q] = 0.f;

#pragma unroll
    for (int kk = 0; kk < 8; kk++) {
        uint32_t af[2][4], bf[4][2];
#pragma unroll
        for (int mt = 0; mt < 2; mt++) {
            int r = wm * 32 + mt * 16;
            af[mt][0] = *(const uint32_t*)&As[(r + g)     * G2_SA + kk * 16 + 2 * tig];
            af[mt][1] = *(const uint32_t*)&As[(r + g + 8) * G2_SA + kk * 16 + 2 * tig];
            af[mt][2] = *(const uint32_t*)&As[(r + g)     * G2_SA + kk * 16 + 8 + 2 * tig];
            af[mt][3] = *(const uint32_t*)&As[(r + g + 8) * G2_SA + kk * 16 + 8 + 2 * tig];
        }
#pragma unroll
        for (int nt = 0; nt < 4; nt++) {
            int c = wn * 32 + nt * 8;
            bf[nt][0] = *(const uint32_t*)&Bs2[(c + g) * G2_SB + kk * 16 + 2 * tig];
            bf[nt][1] = *(const uint32_t*)&Bs2[(c + g) * G2_SB + kk * 16 + 8 + 2 * tig];
        }
#pragma unroll
        for (int mt = 0; mt < 2; mt++)
#pragma unroll
            for (int nt = 0; nt < 4; nt++)
                MMA_F16(acc[mt][nt], af[mt], bf[nt]);
    }

#pragma unroll
    for (int mt = 0; mt < 2; mt++) {
        int r0 = m0 + wm * 32 + mt * 16 + g;
#pragma unroll
        for (int nt = 0; nt < 4; nt++) {
            int c = wn * 32 + nt * 8 + 2 * tig;
            if (r0 < M)
                *(__half2*)(C + (size_t)r0 * 64 + c) =
                    __floats2half2_rn(acc[mt][nt][0], acc[mt][nt][1]);
            if (r0 + 8 < M)
                *(__half2*)(C + (size_t)(r0 + 8) * 64 + c) =
                    __floats2half2_rn(acc[mt][nt][2], acc[mt][nt][3]);
        }
    }
}

// ---------------------------------------------------------------- gather1 (+bias+relu), fp16 in/out, unroll 8
__global__ void k_gather128(const __half* __restrict__ h, __half* __restrict__ agg,
                            const int* __restrict__ off, const int2* __restrict__ ce,
                            const float* __restrict__ dis, const float* __restrict__ bias)
{
    int node = (blockIdx.x * blockDim.x + threadIdx.x) >> 5;
    int lane = threadIdx.x & 31;
    if (node >= N_NODES) return;

    float d = dis[node];
    float dd = d * d;
    float4 acc = ldh4(h + (size_t)node * 128 + lane * 4);
    acc.x *= dd; acc.y *= dd; acc.z *= dd; acc.w *= dd;

    int s = off[node], e = off[node + 1];
    int j = s;
    for (; j + 7 < e; j += 8) {
        int2 p[8];
#pragma unroll
        for (int q = 0; q < 8; q++) p[q] = __ldg(&ce[j + q]);
        float4 v[8];
#pragma unroll
        for (int q = 0; q < 8; q++) v[q] = ldh4(h + (size_t)p[q].x * 128 + lane * 4);
#pragma unroll
        for (int q = 0; q < 8; q++) {
            float n = __int_as_float(p[q].y);
            acc.x = fmaf(v[q].x, n, acc.x); acc.y = fmaf(v[q].y, n, acc.y);
            acc.z = fmaf(v[q].z, n, acc.z); acc.w = fmaf(v[q].w, n, acc.w);
        }
    }
    for (; j + 3 < e; j += 4) {
        int2 p[4];
#pragma unroll
        for (int q = 0; q < 4; q++) p[q] = __ldg(&ce[j + q]);
#pragma unroll
        for (int q = 0; q < 4; q++) {
            float4 v = ldh4(h + (size_t)p[q].x * 128 + lane * 4);
            float n = __int_as_float(p[q].y);
            acc.x = fmaf(v.x, n, acc.x); acc.y = fmaf(v.y, n, acc.y);
            acc.z = fmaf(v.z, n, acc.z); acc.w = fmaf(v.w, n, acc.w);
        }
    }
    for (; j < e; j++) {
        int2 p = __ldg(&ce[j]);
        float n = __int_as_float(p.y);
        float4 v = ldh4(h + (size_t)p.x * 128 + lane * 4);
        acc.x = fmaf(v.x, n, acc.x); acc.y = fmaf(v.y, n, acc.y);
        acc.z = fmaf(v.z, n, acc.z); acc.w = fmaf(v.w, n, acc.w);
    }
    float4 bb = *(const float4*)(bias + lane * 4);
    acc.x = fmaxf(acc.x + bb.x, 0.f); acc.y = fmaxf(acc.y + bb.y, 0.f);
    acc.z = fmaxf(acc.z + bb.z, 0.f); acc.w = fmaxf(acc.w + bb.w, 0.f);
    uint2 st;
    *(__half2*)&st.x = __floats2half2_rn(acc.x, acc.y);
    *(__half2*)&st.y = __floats2half2_rn(acc.z, acc.w);
    *(uint2*)(agg + (size_t)node * 128 + lane * 4) = st;
}

// ---------------------------------------------------------------- gather2 + max-pool (fp16 in), unroll 8
__global__ void k_gather64pool(const __half* __restrict__ h2,
                               const int* __restrict__ off, const int2* __restrict__ ce,
                               const float* __restrict__ dis, const float* __restrict__ b2,
                               const int* __restrict__ batch, float* __restrict__ pool)
{
    int node = (blockIdx.x * blockDim.x + threadIdx.x) >> 5;
    int lane = threadIdx.x & 31;
    if (node >= N_NODES) return;

    float d = dis[node];
    float dd = d * d;
    float2 acc = __half22float2(*(const __half2*)(h2 + (size_t)node * 64 + lane * 2));
    acc.x *= dd; acc.y *= dd;

    int s = off[node], e = off[node + 1];
    int j = s;
    for (; j + 7 < e; j += 8) {
        int2 p[8];
#pragma unroll
        for (int q = 0; q < 8; q++) p[q] = __ldg(&ce[j + q]);
        float2 v[8];
#pragma unroll
        for (int q = 0; q < 8; q++)
            v[q] = __half22float2(*(const __half2*)(h2 + (size_t)p[q].x * 64 + lane * 2));
#pragma unroll
        for (int q = 0; q < 8; q++) {
            float n = __int_as_float(p[q].y);
            acc.x = fmaf(v[q].x, n, acc.x); acc.y = fmaf(v[q].y, n, acc.y);
        }
    }
    for (; j + 3 < e; j += 4) {
        int2 p[4];
#pragma unroll
        for (int q = 0; q < 4; q++) p[q] = __ldg(&ce[j + q]);
#pragma unroll
        for (int q = 0; q < 4; q++) {
            float2 v = __half22float2(*(const __half2*)(h2 + (size_t)p[q].x * 64 + lane * 2));
            float n = __int_as_float(p[q].y);
            acc.x = fmaf(v.x, n, acc.x); acc.y = fmaf(v.y, n, acc.y);
        }
    }
    for (; j < e; j++) {
        int2 p = __ldg(&ce[j]);
        float n = __int_as_float(p.y);
        float2 v = __half22float2(*(const __half2*)(h2 + (size_t)p.x * 64 + lane * 2));
        acc.x = fmaf(v.x, n, acc.x); acc.y = fmaf(v.y, n, acc.y);
    }
    float2 bb = *(const float2*)(b2 + lane * 2);
    acc.x = fmaxf(acc.x + bb.x, 0.f);
    acc.y = fmaxf(acc.y + bb.y, 0.f);

    int gph = batch[node];
    atomicMax((unsigned int*)&pool[gph * H2 + lane * 2],     __float_as_uint(acc.x));
    atomicMax((unsigned int*)&pool[gph * H2 + lane * 2 + 1], __float_as_uint(acc.y));
}

// ---------------------------------------------------------------- final FC
__global__ void k_fc(const float* __restrict__ pool, const float* __restrict__ Wfc,
                     const float* __restrict__ bfc, float* __restrict__ out)
{
    __shared__ float w[H2 * OUT_DIM];
    __shared__ float bb[OUT_DIM];
    int tid = threadIdx.x;
    for (int i = tid; i < H2 * OUT_DIM; i += blockDim.x) w[i] = Wfc[i];
    if (tid < OUT_DIM) bb[tid] = bfc[tid];
    __syncthreads();
    if (tid < N_GRAPHS) {
        float acc[OUT_DIM];
#pragma unroll
        for (int j = 0; j < OUT_DIM; j++) acc[j] = bb[j];
        for (int k = 0; k < H2; k++) {
            float g = pool[tid * H2 + k];
#pragma unroll
            for (int j = 0; j < OUT_DIM; j++) acc[j] = fmaf(g, w[k * OUT_DIM + j], acc[j]);
        }
#pragma unroll
        for (int j = 0; j < OUT_DIM; j++) out[tid * OUT_DIM + j] = acc[j];
    }
}

// ---------------------------------------------------------------- launch
extern "C" void kernel_launch(void* const* d_in, const int* in_sizes, int n_in,
                              void* d_out, int out_size)
{
    const float* x    = (const float*)d_in[0];
    const int*   ei   = (const int*)d_in[1];
    const int*   batch= (const int*)d_in[2];
    const float* W1   = (const float*)d_in[3];
    const float* b1   = (const float*)d_in[4];
    const float* W2   = (const float*)d_in[5];
    const float* b2   = (const float*)d_in[6];
    const float* Wfc  = (const float*)d_in[7];
    const float* bfc  = (const float*)d_in[8];
    float* out = (float*)d_out;

    const int* row = ei;
    const int* col = ei + N_EDGES;

    int *deg, *part, *off, *cursor;
    int2* cedge;
    float *dis, *pool;
    __half *h1, *agg1, *h2;
    cudaGetSymbolAddress((void**)&deg,    g_deg);
    cudaGetSymbolAddress((void**)&part,   g_part);
    cudaGetSymbolAddress((void**)&off,    g_off);
    cudaGetSymbolAddress((void**)&cursor, g_cursor);
    cudaGetSymbolAddress((void**)&dis,    g_dis);
    cudaGetSymbolAddress((void**)&cedge,  g_cedge);
    cudaGetSymbolAddress((void**)&h1,     g_h1);
    cudaGetSymbolAddress((void**)&agg1,   g_agg1);
    cudaGetSymbolAddress((void**)&h2,     g_h2);
    cudaGetSymbolAddress((void**)&pool,   g_pool);

    cudaFuncSetAttribute((const void*)k_gemm_ca<128, 128, 16, 16, 4, 32, 32>,
                         cudaFuncAttributeMaxDynamicSharedMemorySize, G1_SMEM);
    cudaFuncSetAttribute(k_gemm2_f16,
                         cudaFuncAttributeMaxDynamicSharedMemorySize, G2_SMEM);

    cudaStream_t s2;
    cudaStreamCreateWithFlags(&s2, cudaStreamNonBlocking);
    cudaEvent_t evF, evJ;
    cudaEventCreateWithFlags(&evF, cudaEventDisableTiming);
    cudaEventCreateWithFlags(&evJ, cudaEventDisableTiming);

    // fork: CSR build on s2
    cudaEventRecord(evF, 0);
    cudaStreamWaitEvent(s2, evF, 0);
    cudaMemsetAsync(deg, 0, N_NODES * sizeof(int), s2);
    k_count<<<(N_EDGES / 4 + 255) / 256, 256, 0, s2>>>(col, deg);
    k_scan1<<<NB_SCAN, 256, 0, s2>>>(deg, part);
    k_scan2<<<1, 256, 0, s2>>>(part);
    k_scan3<<<NB_SCAN, 256, 0, s2>>>(deg, part, off, cursor, dis);
    k_fill<<<(N_EDGES / 4 + 255) / 256, 256, 0, s2>>>(row, col, dis, cursor, cedge);
    cudaEventRecord(evJ, s2);

    // main: zero pool + GEMM1 (3-stage pipeline)
    cudaMemsetAsync(pool, 0, N_GRAPHS * H2 * sizeof(float), 0);
    k_gemm_ca<128, 128, 16, 16, 4, 32, 32>
        <<<(N_NODES + 127) / 128, 512, G1_SMEM>>>(x, W1, h1, N_NODES, IN_DIM);

    // join; gather1 (+b1+relu) -> agg1 (fp16)
    cudaStreamWaitEvent(0, evJ, 0);
    k_gather128<<<(N_NODES * 32 + 255) / 256, 256>>>(h1, agg1, off, cedge, dis, b1);

    // GEMM2: h2 = agg1 @ W2 (fp16 mma)
    k_gemm2_f16<<<(N_NODES + 127) / 128, 256, G2_SMEM>>>(agg1, W2, h2, N_NODES);

    // gather2 + pool, FC
    k_gather64pool<<<(N_NODES * 32 + 255) / 256, 256>>>(h2, off, cedge, dis, b2, batch, pool);
    k_fc<<<1, 128>>>(pool, Wfc, bfc, out);
}